// round 1
// baseline (speedup 1.0000x reference)
#include <cuda_runtime.h>
#include <math.h>

#define DIN 128
#define HD  128
#define NH  4
#define NMAX 50000
#define ET_MAX 1700000   // E + N self loops
#define GMAX 256

// ---------------- scratch (static device globals; no allocation) ----------------
__device__ float g_h [NMAX * HD];     // GEMM output (pre-attention features)
__device__ float g_x2[NMAX * HD];     // layer output / next layer input
__device__ float g_as[NMAX * NH];
__device__ float g_ad[NMAX * NH];
__device__ int   g_deg[NMAX];
__device__ int   g_off[NMAX + 1];
__device__ int   g_cur[NMAX];
__device__ int   g_csr[ET_MAX];
__device__ float g_bn[2 * HD];        // col sum, col sumsq (zero-init, reset by bn_final)
__device__ float g_scale[HD];
__device__ float g_shift[HD];
__device__ float g_pool[GMAX * HD];   // zero-init, reset by head kernel
__device__ int   g_cnt[GMAX];

// ---------------- helpers ----------------
__device__ __forceinline__ float4 f4add(float4 a, float4 b) {
    return make_float4(a.x + b.x, a.y + b.y, a.z + b.z, a.w + b.w);
}
__device__ __forceinline__ float4 f4max(float4 a, float4 b) {
    return make_float4(fmaxf(a.x, b.x), fmaxf(a.y, b.y), fmaxf(a.z, b.z), fmaxf(a.w, b.w));
}
__device__ __forceinline__ float4 f4lrelu(float4 v) {
    return make_float4(fmaxf(v.x, 0.2f * v.x), fmaxf(v.y, 0.2f * v.y),
                       fmaxf(v.z, 0.2f * v.z), fmaxf(v.w, 0.2f * v.w));
}

// ---------------- CSR build ----------------
__global__ void zero_prep(int n) {
    int i = blockIdx.x * blockDim.x + threadIdx.x;
    if (i < n) { g_deg[i] = 0; g_cur[i] = 0; }
}

__global__ void count_kernel(const int* __restrict__ ei, int E, int n) {
    int i = blockIdx.x * blockDim.x + threadIdx.x;
    if (i >= E + n) return;
    int d = (i < E) ? ei[E + i] : (i - E);
    atomicAdd(&g_deg[d], 1);
}

// single-block exclusive scan of g_deg -> g_off (n up to ~50k)
__global__ void scan_kernel(int n) {
    __shared__ int warp_sums[32];
    __shared__ int carry_sh;
    int t = threadIdx.x;
    int lane = t & 31, wid = t >> 5;
    if (t == 0) { carry_sh = 0; g_off[0] = 0; }
    __syncthreads();
    for (int base = 0; base < n; base += 1024) {
        int i = base + t;
        int v = (i < n) ? g_deg[i] : 0;
        int x = v;
        #pragma unroll
        for (int o = 1; o < 32; o <<= 1) {
            int y = __shfl_up_sync(0xffffffffu, x, o);
            if (lane >= o) x += y;
        }
        if (lane == 31) warp_sums[wid] = x;
        __syncthreads();
        if (wid == 0) {
            int w = warp_sums[lane];
            #pragma unroll
            for (int o = 1; o < 32; o <<= 1) {
                int y = __shfl_up_sync(0xffffffffu, w, o);
                if (lane >= o) w += y;
            }
            warp_sums[lane] = w;
        }
        __syncthreads();
        int warp_off = (wid > 0) ? warp_sums[wid - 1] : 0;
        int incl = carry_sh + warp_off + x;
        if (i < n) g_off[i + 1] = incl;
        __syncthreads();
        if (t == 1023) carry_sh = incl;
        __syncthreads();
    }
}

__global__ void fill_kernel(const int* __restrict__ ei, int E, int n) {
    int i = blockIdx.x * blockDim.x + threadIdx.x;
    if (i >= E + n) return;
    int s, d;
    if (i < E) { s = ei[i]; d = ei[E + i]; }
    else       { s = d = i - E; }
    int pos = g_off[d] + atomicAdd(&g_cur[d], 1);
    g_csr[pos] = s;
}

// ---------------- GEMM: C[M,128] = A[M,128] @ B[128,128] into g_h ----------------
__global__ __launch_bounds__(256) void gemm128(const float* __restrict__ Ain,
                                               const float* __restrict__ B,
                                               int M, int use_x2) {
    const float* A = use_x2 ? (const float*)g_x2 : Ain;
    __shared__ float As[16][132];
    __shared__ float Bs[16][128];
    int tid  = threadIdx.x;
    int row0 = blockIdx.x * 128;
    int tm = (tid >> 4) * 8;
    int tn = (tid & 15) * 8;
    float acc[8][8];
    #pragma unroll
    for (int i = 0; i < 8; i++)
        #pragma unroll
        for (int j = 0; j < 8; j++) acc[i][j] = 0.f;

    for (int k0 = 0; k0 < 128; k0 += 16) {
        #pragma unroll
        for (int l = 0; l < 2; l++) {
            int slot = tid * 2 + l;          // 0..511
            int r  = slot >> 2;              // 0..127
            int kq = slot & 3;               // 0..3
            float4 v = make_float4(0.f, 0.f, 0.f, 0.f);
            int grow = row0 + r;
            if (grow < M) v = *(const float4*)(A + grow * 128 + k0 + kq * 4);
            As[kq * 4 + 0][r] = v.x;
            As[kq * 4 + 1][r] = v.y;
            As[kq * 4 + 2][r] = v.z;
            As[kq * 4 + 3][r] = v.w;
        }
        #pragma unroll
        for (int l = 0; l < 2; l++) {
            int slot = tid * 2 + l;
            int kr = slot >> 5;
            int cq = slot & 31;
            *(float4*)(&Bs[kr][cq * 4]) = *(const float4*)(B + (k0 + kr) * 128 + cq * 4);
        }
        __syncthreads();
        #pragma unroll
        for (int kk = 0; kk < 16; kk++) {
            float a[8], b[8];
            *(float4*)(a)     = *(float4*)(&As[kk][tm]);
            *(float4*)(a + 4) = *(float4*)(&As[kk][tm + 4]);
            *(float4*)(b)     = *(float4*)(&Bs[kk][tn]);
            *(float4*)(b + 4) = *(float4*)(&Bs[kk][tn + 4]);
            #pragma unroll
            for (int i = 0; i < 8; i++)
                #pragma unroll
                for (int j = 0; j < 8; j++)
                    acc[i][j] = fmaf(a[i], b[j], acc[i][j]);
        }
        __syncthreads();
    }
    #pragma unroll
    for (int i = 0; i < 8; i++) {
        int r = row0 + tm + i;
        if (r < M) {
            *(float4*)(g_h + r * 128 + tn)     = make_float4(acc[i][0], acc[i][1], acc[i][2], acc[i][3]);
            *(float4*)(g_h + r * 128 + tn + 4) = make_float4(acc[i][4], acc[i][5], acc[i][6], acc[i][7]);
        }
    }
}

// ---------------- per-node attention logits ----------------
__global__ __launch_bounds__(128) void alpha_kernel(const float* __restrict__ a_s,
                                                    const float* __restrict__ a_d) {
    int i = blockIdx.x;
    int tid = threadIdx.x;
    float v  = g_h[i * HD + tid];
    float ps = v * a_s[tid];
    float pd = v * a_d[tid];
    #pragma unroll
    for (int o = 16; o; o >>= 1) {
        ps += __shfl_down_sync(0xffffffffu, ps, o);
        pd += __shfl_down_sync(0xffffffffu, pd, o);
    }
    if ((tid & 31) == 0) {
        g_as[i * NH + (tid >> 5)] = ps;
        g_ad[i * NH + (tid >> 5)] = pd;
    }
}

// ---------------- GAT aggregation: one block per dst node ----------------
__global__ __launch_bounds__(128) void gat_agg(const float* __restrict__ bias) {
    int d    = blockIdx.x;
    int tid  = threadIdx.x;
    int head = tid >> 5;
    __shared__ float4 sh4[128];
    __shared__ int    ssh[128];
    __shared__ float4 sh_m;
    __shared__ float4 sh_s;

    int beg = g_off[d];
    int deg = g_off[d + 1] - beg;
    float4 adv = ((const float4*)g_ad)[d];

    // pass A: per-head max
    const float NINF = -__int_as_float(0x7f800000);
    float4 mx = make_float4(NINF, NINF, NINF, NINF);
    for (int k = tid; k < deg; k += 128) {
        int s = g_csr[beg + k];
        float4 e = f4lrelu(f4add(((const float4*)g_as)[s], adv));
        mx = f4max(mx, e);
    }
    sh4[tid] = mx;
    __syncthreads();
    for (int o = 64; o; o >>= 1) {
        if (tid < o) sh4[tid] = f4max(sh4[tid], sh4[tid + o]);
        __syncthreads();
    }
    if (tid == 0) sh_m = sh4[0];
    __syncthreads();
    float4 mv = sh_m;

    // pass B: chunks of 128 edges: exp in shared, accumulate payload + sums
    float4 sum = make_float4(0.f, 0.f, 0.f, 0.f);
    float acc0 = 0.f, acc1 = 0.f, acc2 = 0.f, acc3 = 0.f;
    for (int base = 0; base < deg; base += 128) {
        int k = base + tid;
        if (k < deg) {
            int s = g_csr[beg + k];
            float4 e = f4lrelu(f4add(((const float4*)g_as)[s], adv));
            float4 ex = make_float4(__expf(e.x - mv.x), __expf(e.y - mv.y),
                                    __expf(e.z - mv.z), __expf(e.w - mv.w));
            sum = f4add(sum, ex);
            sh4[tid] = ex;
            ssh[tid] = s;
        }
        __syncthreads();
        int cnt = min(128, deg - base);
        const float* exf = (const float*)sh4;
        int j = 0;
        for (; j + 4 <= cnt; j += 4) {
            int s0 = ssh[j], s1 = ssh[j + 1], s2 = ssh[j + 2], s3 = ssh[j + 3];
            float w0 = exf[(j    ) * 4 + head];
            float w1 = exf[(j + 1) * 4 + head];
            float w2 = exf[(j + 2) * 4 + head];
            float w3 = exf[(j + 3) * 4 + head];
            acc0 = fmaf(g_h[s0 * HD + tid], w0, acc0);
            acc1 = fmaf(g_h[s1 * HD + tid], w1, acc1);
            acc2 = fmaf(g_h[s2 * HD + tid], w2, acc2);
            acc3 = fmaf(g_h[s3 * HD + tid], w3, acc3);
        }
        for (; j < cnt; j++)
            acc0 = fmaf(g_h[ssh[j] * HD + tid], exf[j * 4 + head], acc0);
        __syncthreads();
    }
    // reduce sums
    sh4[tid] = sum;
    __syncthreads();
    for (int o = 64; o; o >>= 1) {
        if (tid < o) sh4[tid] = f4add(sh4[tid], sh4[tid + o]);
        __syncthreads();
    }
    if (tid == 0) sh_s = sh4[0];
    __syncthreads();
    float sv  = ((const float*)&sh_s)[head];
    float inv = 1.0f / (sv + 1e-16f);
    float o   = (acc0 + acc1 + acc2 + acc3) * inv + bias[tid];
    g_x2[d * HD + tid] = fmaxf(o, 0.0f);
}

// ---------------- BatchNorm ----------------
__global__ void bn_reduce(int n) {
    int c = threadIdx.x;
    float s = 0.f, q = 0.f;
    for (int r = blockIdx.x; r < n; r += gridDim.x) {
        float v = g_x2[r * HD + c];
        s += v; q += v * v;
    }
    atomicAdd(&g_bn[c], s);
    atomicAdd(&g_bn[HD + c], q);
}

__global__ void bn_final(const float* __restrict__ gamma, const float* __restrict__ beta, int n) {
    int c = threadIdx.x;
    float fn = (float)n;
    float mu  = g_bn[c] / fn;
    float var = g_bn[HD + c] / fn - mu * mu;
    float inv = rsqrtf(var + 1e-5f);
    float sc  = gamma[c] * inv;
    g_scale[c] = sc;
    g_shift[c] = beta[c] - mu * sc;
    g_bn[c] = 0.f;            // reset for next use / next graph replay
    g_bn[HD + c] = 0.f;
}

__global__ void bn_apply(int total4) {
    float4* p = (float4*)g_x2;
    for (int i = blockIdx.x * blockDim.x + threadIdx.x; i < total4; i += gridDim.x * blockDim.x) {
        float4 v  = p[i];
        int   c4  = i & 31;
        float4 sc = ((const float4*)g_scale)[c4];
        float4 sf = ((const float4*)g_shift)[c4];
        v.x = fmaf(v.x, sc.x, sf.x);
        v.y = fmaf(v.y, sc.y, sf.y);
        v.z = fmaf(v.z, sc.z, sf.z);
        v.w = fmaf(v.w, sc.w, sf.w);
        p[i] = v;
    }
}

// ---------------- pooling ----------------
__global__ __launch_bounds__(128) void pool_kernel(const int* __restrict__ batch, int n) {
    int t = threadIdx.x;
    for (int i = blockIdx.x; i < n; i += gridDim.x) {
        int g = batch[i];
        atomicAdd(&g_pool[g * HD + t], g_x2[i * HD + t]);
        if (t == 0) atomicAdd(&g_cnt[g], 1);
    }
}

// ---------------- MLP head (also resets pool scratch) ----------------
__global__ __launch_bounds__(128) void head_kernel(const float* __restrict__ L1W,
                                                   const float* __restrict__ L1b,
                                                   const float* __restrict__ L2W,
                                                   const float* __restrict__ L2b,
                                                   float* __restrict__ out) {
    int g = blockIdx.x, t = threadIdx.x;
    __shared__ float p[128], r0[128], r1[128];
    int c = g_cnt[g];
    float denom = (float)(c > 0 ? c : 1);
    p[t] = g_pool[g * HD + t] / denom;
    g_pool[g * HD + t] = 0.f;
    if (t == 0) g_cnt[g] = 0;
    __syncthreads();
    float acc = L1b[t];
    #pragma unroll 8
    for (int k = 0; k < 128; k++)
        acc = fmaf(p[k], L1W[k * HD + t], acc);
    float z = fmaxf(acc, 0.f);
    r0[t] = z * L2W[t * 2 + 0];
    r1[t] = z * L2W[t * 2 + 1];
    __syncthreads();
    for (int o = 64; o; o >>= 1) {
        if (t < o) { r0[t] += r0[t + o]; r1[t] += r1[t + o]; }
        __syncthreads();
    }
    if (t == 0) {
        out[g * 2 + 0] = r0[0] + L2b[0];
        out[g * 2 + 1] = r1[0] + L2b[1];
    }
}

// ---------------- launch ----------------
extern "C" void kernel_launch(void* const* d_in, const int* in_sizes, int n_in,
                              void* d_out, int out_size) {
    const float* x    = (const float*)d_in[0];
    const int*   ei   = (const int*)  d_in[1];
    const int*   batch= (const int*)  d_in[2];
    const float* W1   = (const float*)d_in[3];
    const float* a1s  = (const float*)d_in[4];
    const float* a1d  = (const float*)d_in[5];
    const float* b1   = (const float*)d_in[6];
    const float* bn1g = (const float*)d_in[7];
    const float* bn1b = (const float*)d_in[8];
    const float* W2   = (const float*)d_in[9];
    const float* a2s  = (const float*)d_in[10];
    const float* a2d  = (const float*)d_in[11];
    const float* b2   = (const float*)d_in[12];
    const float* bn2g = (const float*)d_in[13];
    const float* bn2b = (const float*)d_in[14];
    const float* L1W  = (const float*)d_in[15];
    const float* L1b  = (const float*)d_in[16];
    const float* L2W  = (const float*)d_in[17];
    const float* L2b  = (const float*)d_in[18];

    int n = in_sizes[0] / HD;      // 50000
    int E = in_sizes[1] / 2;       // 1600000
    int G = out_size / 2;          // 256
    int ET = E + n;

    // CSR build (self loops appended)
    zero_prep  <<<(n  + 255) / 256, 256>>>(n);
    count_kernel<<<(ET + 255) / 256, 256>>>(ei, E, n);
    scan_kernel<<<1, 1024>>>(n);
    fill_kernel<<<(ET + 255) / 256, 256>>>(ei, E, n);

    int gb = (n + 127) / 128;

    // Layer 1
    gemm128    <<<gb, 256>>>(x, W1, n, 0);
    alpha_kernel<<<n, 128>>>(a1s, a1d);
    gat_agg    <<<n, 128>>>(b1);
    bn_reduce  <<<512, 128>>>(n);
    bn_final   <<<1, 128>>>(bn1g, bn1b, n);
    bn_apply   <<<2048, 256>>>(n * 32);

    // Layer 2
    gemm128    <<<gb, 256>>>(nullptr, W2, n, 1);
    alpha_kernel<<<n, 128>>>(a2s, a2d);
    gat_agg    <<<n, 128>>>(b2);
    bn_reduce  <<<512, 128>>>(n);
    bn_final   <<<1, 128>>>(bn2g, bn2b, n);
    bn_apply   <<<2048, 256>>>(n * 32);

    // Pool + head
    pool_kernel<<<2048, 128>>>(batch, n);
    head_kernel<<<G, 128>>>(L1W, L1b, L2W, L2b, (float*)d_out);
}

// round 2
// speedup vs baseline: 1.1124x; 1.1124x over previous
#include <cuda_runtime.h>
#include <math.h>

#define DIN 128
#define HD  128
#define NH  4
#define NMAX 50000
#define ET_MAX 1700000   // E + N self loops
#define GMAX 256

// ---------------- scratch (static device globals; no allocation) ----------------
__device__ float g_h [NMAX * HD];     // GEMM output (pre-attention features)
__device__ float g_x2[NMAX * HD];     // layer output / next layer input
__device__ float g_as[NMAX * NH];
__device__ float g_ad[NMAX * NH];
__device__ int   g_deg[NMAX];
__device__ int   g_off[NMAX + 1];
__device__ int   g_cur[NMAX];
__device__ int   g_csr[ET_MAX];
__device__ float g_bn[2 * HD];        // col sum, col sumsq (zero-init, reset by bn_final)
__device__ float g_scale[HD];
__device__ float g_shift[HD];
__device__ float g_pool[GMAX * HD];   // zero-init, reset by head kernel
__device__ int   g_cnt[GMAX];

// ---------------- helpers ----------------
__device__ __forceinline__ float4 f4add(float4 a, float4 b) {
    return make_float4(a.x + b.x, a.y + b.y, a.z + b.z, a.w + b.w);
}
__device__ __forceinline__ float4 f4lrelu(float4 v) {
    return make_float4(fmaxf(v.x, 0.2f * v.x), fmaxf(v.y, 0.2f * v.y),
                       fmaxf(v.z, 0.2f * v.z), fmaxf(v.w, 0.2f * v.w));
}

// ---------------- CSR build ----------------
__global__ void zero_prep(int n) {
    int i = blockIdx.x * blockDim.x + threadIdx.x;
    if (i < n) { g_deg[i] = 0; g_cur[i] = 0; }
}

__global__ void count_kernel(const int* __restrict__ ei, int E, int n) {
    int i = blockIdx.x * blockDim.x + threadIdx.x;
    if (i >= E + n) return;
    int d = (i < E) ? ei[E + i] : (i - E);
    atomicAdd(&g_deg[d], 1);
}

// single-block exclusive scan of g_deg -> g_off (n up to ~50k)
__global__ void scan_kernel(int n) {
    __shared__ int warp_sums[32];
    __shared__ int carry_sh;
    int t = threadIdx.x;
    int lane = t & 31, wid = t >> 5;
    if (t == 0) { carry_sh = 0; g_off[0] = 0; }
    __syncthreads();
    for (int base = 0; base < n; base += 1024) {
        int i = base + t;
        int v = (i < n) ? g_deg[i] : 0;
        int x = v;
        #pragma unroll
        for (int o = 1; o < 32; o <<= 1) {
            int y = __shfl_up_sync(0xffffffffu, x, o);
            if (lane >= o) x += y;
        }
        if (lane == 31) warp_sums[wid] = x;
        __syncthreads();
        if (wid == 0) {
            int w = warp_sums[lane];
            #pragma unroll
            for (int o = 1; o < 32; o <<= 1) {
                int y = __shfl_up_sync(0xffffffffu, w, o);
                if (lane >= o) w += y;
            }
            warp_sums[lane] = w;
        }
        __syncthreads();
        int warp_off = (wid > 0) ? warp_sums[wid - 1] : 0;
        int incl = carry_sh + warp_off + x;
        if (i < n) g_off[i + 1] = incl;
        __syncthreads();
        if (t == 1023) carry_sh = incl;
        __syncthreads();
    }
}

__global__ void fill_kernel(const int* __restrict__ ei, int E, int n) {
    int i = blockIdx.x * blockDim.x + threadIdx.x;
    if (i >= E + n) return;
    int s, d;
    if (i < E) { s = ei[i]; d = ei[E + i]; }
    else       { s = d = i - E; }
    int pos = g_off[d] + atomicAdd(&g_cur[d], 1);
    g_csr[pos] = s;
}

// ---------------- GEMM: g_h[M,128] = A[M,128] @ B[128,128], fused:
//   - optional per-column affine on A (folded BatchNorm)
//   - fused attention logits g_as/g_ad (dot with a_src/a_dst per head)
__global__ __launch_bounds__(256) void gemm128(const float* __restrict__ Ain,
                                               const float* __restrict__ B,
                                               int M, int use_x2, int use_scale,
                                               const float* __restrict__ a_src,
                                               const float* __restrict__ a_dst) {
    const float* A = use_x2 ? (const float*)g_x2 : Ain;
    __shared__ float As[16][132];
    __shared__ float Bs[16][128];
    __shared__ float sA[128][NH];
    __shared__ float sD[128][NH];
    int tid  = threadIdx.x;
    int row0 = blockIdx.x * 128;
    int tm = (tid >> 4) * 8;
    int tn = (tid & 15) * 8;

    // zero alpha accumulators
    #pragma unroll
    for (int l = 0; l < 2; l++) {
        int idx = tid * 2 + l;      // 0..511
        sA[idx >> 2][idx & 3] = 0.f;
        sD[idx >> 2][idx & 3] = 0.f;
    }

    float acc[8][8];
    #pragma unroll
    for (int i = 0; i < 8; i++)
        #pragma unroll
        for (int j = 0; j < 8; j++) acc[i][j] = 0.f;

    for (int k0 = 0; k0 < 128; k0 += 16) {
        #pragma unroll
        for (int l = 0; l < 2; l++) {
            int slot = tid * 2 + l;          // 0..511
            int r  = slot >> 2;              // 0..127
            int kq = slot & 3;               // 0..3
            float4 v = make_float4(0.f, 0.f, 0.f, 0.f);
            int grow = row0 + r;
            if (grow < M) {
                v = *(const float4*)(A + grow * 128 + k0 + kq * 4);
                if (use_scale) {
                    float4 sc = *(const float4*)(g_scale + k0 + kq * 4);
                    float4 sf = *(const float4*)(g_shift + k0 + kq * 4);
                    v.x = fmaf(v.x, sc.x, sf.x);
                    v.y = fmaf(v.y, sc.y, sf.y);
                    v.z = fmaf(v.z, sc.z, sf.z);
                    v.w = fmaf(v.w, sc.w, sf.w);
                }
            }
            As[kq * 4 + 0][r] = v.x;
            As[kq * 4 + 1][r] = v.y;
            As[kq * 4 + 2][r] = v.z;
            As[kq * 4 + 3][r] = v.w;
        }
        #pragma unroll
        for (int l = 0; l < 2; l++) {
            int slot = tid * 2 + l;
            int kr = slot >> 5;
            int cq = slot & 31;
            *(float4*)(&Bs[kr][cq * 4]) = *(const float4*)(B + (k0 + kr) * 128 + cq * 4);
        }
        __syncthreads();
        #pragma unroll
        for (int kk = 0; kk < 16; kk++) {
            float a[8], b[8];
            *(float4*)(a)     = *(float4*)(&As[kk][tm]);
            *(float4*)(a + 4) = *(float4*)(&As[kk][tm + 4]);
            *(float4*)(b)     = *(float4*)(&Bs[kk][tn]);
            *(float4*)(b + 4) = *(float4*)(&Bs[kk][tn + 4]);
            #pragma unroll
            for (int i = 0; i < 8; i++)
                #pragma unroll
                for (int j = 0; j < 8; j++)
                    acc[i][j] = fmaf(a[i], b[j], acc[i][j]);
        }
        __syncthreads();
    }

    // write C + fused per-head attention logit partials
    float asv[8], adv[8];
    #pragma unroll
    for (int j = 0; j < 8; j++) { asv[j] = a_src[tn + j]; adv[j] = a_dst[tn + j]; }
    int head = tn >> 5;
    #pragma unroll
    for (int i = 0; i < 8; i++) {
        int r = row0 + tm + i;
        float ps = 0.f, pd = 0.f;
        #pragma unroll
        for (int j = 0; j < 8; j++) {
            ps = fmaf(acc[i][j], asv[j], ps);
            pd = fmaf(acc[i][j], adv[j], pd);
        }
        if (r < M) {
            *(float4*)(g_h + r * 128 + tn)     = make_float4(acc[i][0], acc[i][1], acc[i][2], acc[i][3]);
            *(float4*)(g_h + r * 128 + tn + 4) = make_float4(acc[i][4], acc[i][5], acc[i][6], acc[i][7]);
            atomicAdd(&sA[tm + i][head], ps);
            atomicAdd(&sD[tm + i][head], pd);
        }
    }
    __syncthreads();
    #pragma unroll
    for (int l = 0; l < 2; l++) {
        int idx = tid * 2 + l;      // 0..511
        int r = idx >> 2, h = idx & 3;
        if (row0 + r < M) {
            g_as[(row0 + r) * NH + h] = sA[r][h];
            g_ad[(row0 + r) * NH + h] = sD[r][h];
        }
    }
}

// ---------------- GAT aggregation: one block per dst node, single pass ----------------
// softmax without max-subtraction: exp args have |e| < ~3 here, numerically safe.
__global__ __launch_bounds__(128) void gat_agg(const float* __restrict__ bias) {
    int d    = blockIdx.x;
    int tid  = threadIdx.x;
    int head = tid >> 5;
    __shared__ float4 sh4[128];
    __shared__ int    ssh[128];
    __shared__ float4 sh_s;

    int beg = g_off[d];
    int deg = g_off[d + 1] - beg;
    float4 adv = ((const float4*)g_ad)[d];

    float4 sum = make_float4(0.f, 0.f, 0.f, 0.f);
    float acc0 = 0.f, acc1 = 0.f, acc2 = 0.f, acc3 = 0.f;
    for (int base = 0; base < deg; base += 128) {
        int k = base + tid;
        if (k < deg) {
            int s = g_csr[beg + k];
            float4 e = f4lrelu(f4add(((const float4*)g_as)[s], adv));
            float4 ex = make_float4(__expf(e.x), __expf(e.y), __expf(e.z), __expf(e.w));
            sum = f4add(sum, ex);
            sh4[tid] = ex;
            ssh[tid] = s;
        }
        __syncthreads();
        int cnt = min(128, deg - base);
        const float* exf = (const float*)sh4;
        int j = 0;
        for (; j + 4 <= cnt; j += 4) {
            int s0 = ssh[j], s1 = ssh[j + 1], s2 = ssh[j + 2], s3 = ssh[j + 3];
            float w0 = exf[(j    ) * 4 + head];
            float w1 = exf[(j + 1) * 4 + head];
            float w2 = exf[(j + 2) * 4 + head];
            float w3 = exf[(j + 3) * 4 + head];
            acc0 = fmaf(g_h[s0 * HD + tid], w0, acc0);
            acc1 = fmaf(g_h[s1 * HD + tid], w1, acc1);
            acc2 = fmaf(g_h[s2 * HD + tid], w2, acc2);
            acc3 = fmaf(g_h[s3 * HD + tid], w3, acc3);
        }
        for (; j < cnt; j++)
            acc0 = fmaf(g_h[ssh[j] * HD + tid], exf[j * 4 + head], acc0);
        __syncthreads();
    }
    // reduce per-head exp-sums
    sh4[tid] = sum;
    __syncthreads();
    for (int o = 64; o; o >>= 1) {
        if (tid < o) sh4[tid] = f4add(sh4[tid], sh4[tid + o]);
        __syncthreads();
    }
    if (tid == 0) sh_s = sh4[0];
    __syncthreads();
    float sv  = ((const float*)&sh_s)[head];
    float inv = 1.0f / (sv + 1e-16f);
    float o   = (acc0 + acc1 + acc2 + acc3) * inv + bias[tid];
    g_x2[d * HD + tid] = fmaxf(o, 0.0f);
}

// ---------------- BatchNorm stats (apply is folded downstream) ----------------
__global__ void bn_reduce(int n) {
    int c = threadIdx.x;
    float s = 0.f, q = 0.f;
    for (int r = blockIdx.x; r < n; r += gridDim.x) {
        float v = g_x2[r * HD + c];
        s += v; q += v * v;
    }
    atomicAdd(&g_bn[c], s);
    atomicAdd(&g_bn[HD + c], q);
}

__global__ void bn_final(const float* __restrict__ gamma, const float* __restrict__ beta, int n) {
    int c = threadIdx.x;
    float fn = (float)n;
    float mu  = g_bn[c] / fn;
    float var = g_bn[HD + c] / fn - mu * mu;
    float inv = rsqrtf(var + 1e-5f);
    float sc  = gamma[c] * inv;
    g_scale[c] = sc;
    g_shift[c] = beta[c] - mu * sc;
    g_bn[c] = 0.f;            // reset for next graph replay
    g_bn[HD + c] = 0.f;
}

// ---------------- pooling: batch is sorted -> segmented register accumulation ----------------
__global__ __launch_bounds__(128) void pool_kernel(const int* __restrict__ batch, int n, int chunk) {
    int i0 = blockIdx.x * chunk;
    if (i0 >= n) return;
    int i1 = min(n, i0 + chunk);
    int t  = threadIdx.x;
    float acc = 0.f;
    int cur = batch[i0];
    int run = 0;
    for (int i = i0; i < i1; i++) {
        int g = batch[i];
        if (g != cur) {
            atomicAdd(&g_pool[cur * HD + t], acc);
            if (t == 0) atomicAdd(&g_cnt[cur], run);
            acc = 0.f; run = 0; cur = g;
        }
        acc += g_x2[i * HD + t];
        run++;
    }
    atomicAdd(&g_pool[cur * HD + t], acc);
    if (t == 0) atomicAdd(&g_cnt[cur], run);
}

// ---------------- MLP head: applies layer-2 BN affine to pooled means, resets scratch ----------------
__global__ __launch_bounds__(128) void head_kernel(const float* __restrict__ L1W,
                                                   const float* __restrict__ L1b,
                                                   const float* __restrict__ L2W,
                                                   const float* __restrict__ L2b,
                                                   float* __restrict__ out) {
    int g = blockIdx.x, t = threadIdx.x;
    __shared__ float p[128], r0[128], r1[128];
    int c = g_cnt[g];
    float denom = (float)(c > 0 ? c : 1);
    // BN2 commutes with mean pooling (affine): apply scale/shift post-pool
    p[t] = fmaf(g_pool[g * HD + t] / denom, g_scale[t], g_shift[t]);
    g_pool[g * HD + t] = 0.f;
    if (t == 0) g_cnt[g] = 0;
    __syncthreads();
    float acc = L1b[t];
    #pragma unroll 8
    for (int k = 0; k < 128; k++)
        acc = fmaf(p[k], L1W[k * HD + t], acc);
    float z = fmaxf(acc, 0.f);
    r0[t] = z * L2W[t * 2 + 0];
    r1[t] = z * L2W[t * 2 + 1];
    __syncthreads();
    for (int o = 64; o; o >>= 1) {
        if (t < o) { r0[t] += r0[t + o]; r1[t] += r1[t + o]; }
        __syncthreads();
    }
    if (t == 0) {
        out[g * 2 + 0] = r0[0] + L2b[0];
        out[g * 2 + 1] = r1[0] + L2b[1];
    }
}

// ---------------- launch ----------------
extern "C" void kernel_launch(void* const* d_in, const int* in_sizes, int n_in,
                              void* d_out, int out_size) {
    const float* x    = (const float*)d_in[0];
    const int*   ei   = (const int*)  d_in[1];
    const int*   batch= (const int*)  d_in[2];
    const float* W1   = (const float*)d_in[3];
    const float* a1s  = (const float*)d_in[4];
    const float* a1d  = (const float*)d_in[5];
    const float* b1   = (const float*)d_in[6];
    const float* bn1g = (const float*)d_in[7];
    const float* bn1b = (const float*)d_in[8];
    const float* W2   = (const float*)d_in[9];
    const float* a2s  = (const float*)d_in[10];
    const float* a2d  = (const float*)d_in[11];
    const float* b2   = (const float*)d_in[12];
    const float* bn2g = (const float*)d_in[13];
    const float* bn2b = (const float*)d_in[14];
    const float* L1W  = (const float*)d_in[15];
    const float* L1b  = (const float*)d_in[16];
    const float* L2W  = (const float*)d_in[17];
    const float* L2b  = (const float*)d_in[18];

    int n = in_sizes[0] / HD;      // 50000
    int E = in_sizes[1] / 2;       // 1600000
    int G = out_size / 2;          // 256
    int ET = E + n;

    // CSR build (self loops appended)
    zero_prep   <<<(n  + 255) / 256, 256>>>(n);
    count_kernel<<<(ET + 255) / 256, 256>>>(ei, E, n);
    scan_kernel <<<1, 1024>>>(n);
    fill_kernel <<<(ET + 255) / 256, 256>>>(ei, E, n);

    int gb = (n + 127) / 128;

    // Layer 1 (no input affine)
    gemm128<<<gb, 256>>>(x, W1, n, 0, 0, a1s, a1d);
    gat_agg<<<n, 128>>>(b1);
    bn_reduce<<<512, 128>>>(n);
    bn_final <<<1, 128>>>(bn1g, bn1b, n);

    // Layer 2 (BN1 affine folded into A-tile load)
    gemm128<<<gb, 256>>>(nullptr, W2, n, 1, 1, a2s, a2d);
    gat_agg<<<n, 128>>>(b2);
    bn_reduce<<<512, 128>>>(n);
    bn_final <<<1, 128>>>(bn2g, bn2b, n);   // BN2 affine applied in head after pooling

    // Pool + head
    pool_kernel<<<(n + 255) / 256, 128>>>(batch, n, 256);
    head_kernel<<<G, 128>>>(L1W, L1b, L2W, L2b, (float*)d_out);
}

// round 4
// speedup vs baseline: 1.1798x; 1.0606x over previous
#include <cuda_runtime.h>
#include <cuda_fp16.h>
#include <math.h>

#define DIN 128
#define HD  128
#define NH  4
#define NMAX 50000
#define ET_MAX 1700000   // E + N self loops
#define GMAX 256

// ---------------- scratch (static device globals; no allocation) ----------------
__device__ __half g_h [NMAX * HD];    // GEMM output (pre-attention features), fp16 payload
__device__ float g_x2[NMAX * HD];     // layer output / next layer input
__device__ float g_as[NMAX * NH];
__device__ float g_ad[NMAX * NH];
__device__ int   g_deg[NMAX];
__device__ int   g_off[NMAX + 1];
__device__ int   g_cur[NMAX];
__device__ int   g_csr[ET_MAX];
__device__ float g_bn[2 * HD];        // col sum, col sumsq (zero-init, reset by bn_final)
__device__ float g_scale[HD];
__device__ float g_shift[HD];
__device__ float g_pool[GMAX * HD];   // zero-init, reset by head kernel
__device__ int   g_cnt[GMAX];

// ---------------- helpers ----------------
__device__ __forceinline__ float4 f4add(float4 a, float4 b) {
    return make_float4(a.x + b.x, a.y + b.y, a.z + b.z, a.w + b.w);
}
__device__ __forceinline__ float4 f4lrelu(float4 v) {
    return make_float4(fmaxf(v.x, 0.2f * v.x), fmaxf(v.y, 0.2f * v.y),
                       fmaxf(v.z, 0.2f * v.z), fmaxf(v.w, 0.2f * v.w));
}
__device__ __forceinline__ unsigned h2_as_u32(__half2 h) {
    return *reinterpret_cast<unsigned*>(&h);
}

// ---------------- CSR build ----------------
__global__ void zero_prep(int n) {
    int i = blockIdx.x * blockDim.x + threadIdx.x;
    if (i < n) { g_deg[i] = 0; g_cur[i] = 0; }
}

__global__ void count_kernel(const int* __restrict__ ei, int E, int n) {
    int i = blockIdx.x * blockDim.x + threadIdx.x;
    if (i >= E + n) return;
    int d = (i < E) ? ei[E + i] : (i - E);
    atomicAdd(&g_deg[d], 1);
}

// single-block exclusive scan of g_deg -> g_off
__global__ void scan_kernel(int n) {
    __shared__ int warp_sums[32];
    __shared__ int carry_sh;
    int t = threadIdx.x;
    int lane = t & 31, wid = t >> 5;
    if (t == 0) { carry_sh = 0; g_off[0] = 0; }
    __syncthreads();
    for (int base = 0; base < n; base += 1024) {
        int i = base + t;
        int v = (i < n) ? g_deg[i] : 0;
        int x = v;
        #pragma unroll
        for (int o = 1; o < 32; o <<= 1) {
            int y = __shfl_up_sync(0xffffffffu, x, o);
            if (lane >= o) x += y;
        }
        if (lane == 31) warp_sums[wid] = x;
        __syncthreads();
        if (wid == 0) {
            int w = warp_sums[lane];
            #pragma unroll
            for (int o = 1; o < 32; o <<= 1) {
                int y = __shfl_up_sync(0xffffffffu, w, o);
                if (lane >= o) w += y;
            }
            warp_sums[lane] = w;
        }
        __syncthreads();
        int warp_off = (wid > 0) ? warp_sums[wid - 1] : 0;
        int incl = carry_sh + warp_off + x;
        if (i < n) g_off[i + 1] = incl;
        __syncthreads();
        if (t == 1023) carry_sh = incl;
        __syncthreads();
    }
}

__global__ void fill_kernel(const int* __restrict__ ei, int E, int n) {
    int i = blockIdx.x * blockDim.x + threadIdx.x;
    if (i >= E + n) return;
    int s, d;
    if (i < E) { s = ei[i]; d = ei[E + i]; }
    else       { s = d = i - E; }
    int pos = g_off[d] + atomicAdd(&g_cur[d], 1);
    g_csr[pos] = s;
}

// ---------------- GEMM: g_h[M,128](fp16) = A[M,128] @ B[128,128], fused:
//   - optional per-column affine on A (folded BatchNorm)
//   - fused attention logits g_as/g_ad (dot with a_src/a_dst per head, fp32 acc)
__global__ __launch_bounds__(256) void gemm128(const float* __restrict__ Ain,
                                               const float* __restrict__ B,
                                               int M, int use_x2, int use_scale,
                                               const float* __restrict__ a_src,
                                               const float* __restrict__ a_dst) {
    const float* A = use_x2 ? (const float*)g_x2 : Ain;
    __shared__ float As[16][132];
    __shared__ float Bs[16][128];
    __shared__ float sA[128][NH];
    __shared__ float sD[128][NH];
    int tid  = threadIdx.x;
    int row0 = blockIdx.x * 128;
    int tm = (tid >> 4) * 8;
    int tn = (tid & 15) * 8;

    #pragma unroll
    for (int l = 0; l < 2; l++) {
        int idx = tid * 2 + l;
        sA[idx >> 2][idx & 3] = 0.f;
        sD[idx >> 2][idx & 3] = 0.f;
    }

    float acc[8][8];
    #pragma unroll
    for (int i = 0; i < 8; i++)
        #pragma unroll
        for (int j = 0; j < 8; j++) acc[i][j] = 0.f;

    for (int k0 = 0; k0 < 128; k0 += 16) {
        #pragma unroll
        for (int l = 0; l < 2; l++) {
            int slot = tid * 2 + l;
            int r  = slot >> 2;
            int kq = slot & 3;
            float4 v = make_float4(0.f, 0.f, 0.f, 0.f);
            int grow = row0 + r;
            if (grow < M) {
                v = *(const float4*)(A + grow * 128 + k0 + kq * 4);
                if (use_scale) {
                    float4 sc = *(const float4*)(g_scale + k0 + kq * 4);
                    float4 sf = *(const float4*)(g_shift + k0 + kq * 4);
                    v.x = fmaf(v.x, sc.x, sf.x);
                    v.y = fmaf(v.y, sc.y, sf.y);
                    v.z = fmaf(v.z, sc.z, sf.z);
                    v.w = fmaf(v.w, sc.w, sf.w);
                }
            }
            As[kq * 4 + 0][r] = v.x;
            As[kq * 4 + 1][r] = v.y;
            As[kq * 4 + 2][r] = v.z;
            As[kq * 4 + 3][r] = v.w;
        }
        #pragma unroll
        for (int l = 0; l < 2; l++) {
            int slot = tid * 2 + l;
            int kr = slot >> 5;
            int cq = slot & 31;
            *(float4*)(&Bs[kr][cq * 4]) = *(const float4*)(B + (k0 + kr) * 128 + cq * 4);
        }
        __syncthreads();
        #pragma unroll
        for (int kk = 0; kk < 16; kk++) {
            float a[8], b[8];
            *(float4*)(a)     = *(float4*)(&As[kk][tm]);
            *(float4*)(a + 4) = *(float4*)(&As[kk][tm + 4]);
            *(float4*)(b)     = *(float4*)(&Bs[kk][tn]);
            *(float4*)(b + 4) = *(float4*)(&Bs[kk][tn + 4]);
            #pragma unroll
            for (int i = 0; i < 8; i++)
                #pragma unroll
                for (int j = 0; j < 8; j++)
                    acc[i][j] = fmaf(a[i], b[j], acc[i][j]);
        }
        __syncthreads();
    }

    // epilogue: fp16 store + fused per-head attention logit partials (fp32)
    float asv[8], adv[8];
    #pragma unroll
    for (int j = 0; j < 8; j++) { asv[j] = a_src[tn + j]; adv[j] = a_dst[tn + j]; }
    int head = tn >> 5;
    #pragma unroll
    for (int i = 0; i < 8; i++) {
        int r = row0 + tm + i;
        float ps = 0.f, pd = 0.f;
        #pragma unroll
        for (int j = 0; j < 8; j++) {
            ps = fmaf(acc[i][j], asv[j], ps);
            pd = fmaf(acc[i][j], adv[j], pd);
        }
        if (r < M) {
            uint4 pk;
            pk.x = h2_as_u32(__floats2half2_rn(acc[i][0], acc[i][1]));
            pk.y = h2_as_u32(__floats2half2_rn(acc[i][2], acc[i][3]));
            pk.z = h2_as_u32(__floats2half2_rn(acc[i][4], acc[i][5]));
            pk.w = h2_as_u32(__floats2half2_rn(acc[i][6], acc[i][7]));
            *(uint4*)(&g_h[r * 128 + tn]) = pk;
            atomicAdd(&sA[tm + i][head], ps);
            atomicAdd(&sD[tm + i][head], pd);
        }
    }
    __syncthreads();
    #pragma unroll
    for (int l = 0; l < 2; l++) {
        int idx = tid * 2 + l;
        int r = idx >> 2, h = idx & 3;
        if (row0 + r < M) {
            g_as[(row0 + r) * NH + h] = sA[r][h];
            g_ad[(row0 + r) * NH + h] = sD[r][h];
        }
    }
}

// ---------------- GAT aggregation: one block per dst node, single pass, fp16 payload ----------------
__global__ __launch_bounds__(128) void gat_agg(const float* __restrict__ bias) {
    int d    = blockIdx.x;
    int tid  = threadIdx.x;
    int lane = tid & 31;
    int warp = tid >> 5;
    int head = warp;
    __shared__ float4 sh4[128];
    __shared__ int    ssh[128];
    __shared__ float4 wsum[4];

    int beg = g_off[d];
    int deg = g_off[d + 1] - beg;
    float4 adv = ((const float4*)g_ad)[d];

    float4 sum = make_float4(0.f, 0.f, 0.f, 0.f);
    float acc0 = 0.f, acc1 = 0.f, acc2 = 0.f, acc3 = 0.f;
    for (int base = 0; base < deg; base += 128) {
        int k = base + tid;
        if (k < deg) {
            int s = g_csr[beg + k];
            float4 e = f4lrelu(f4add(((const float4*)g_as)[s], adv));
            float4 ex = make_float4(__expf(e.x), __expf(e.y), __expf(e.z), __expf(e.w));
            sum = f4add(sum, ex);
            sh4[tid] = ex;
            ssh[tid] = s;
        }
        __syncthreads();
        int cnt = min(128, deg - base);
        const float* exf = (const float*)sh4;
        int j = 0;
        for (; j + 4 <= cnt; j += 4) {
            int s0 = ssh[j], s1 = ssh[j + 1], s2 = ssh[j + 2], s3 = ssh[j + 3];
            float w0 = exf[(j    ) * 4 + head];
            float w1 = exf[(j + 1) * 4 + head];
            float w2 = exf[(j + 2) * 4 + head];
            float w3 = exf[(j + 3) * 4 + head];
            acc0 = fmaf(__half2float(g_h[s0 * HD + tid]), w0, acc0);
            acc1 = fmaf(__half2float(g_h[s1 * HD + tid]), w1, acc1);
            acc2 = fmaf(__half2float(g_h[s2 * HD + tid]), w2, acc2);
            acc3 = fmaf(__half2float(g_h[s3 * HD + tid]), w3, acc3);
        }
        for (; j < cnt; j++)
            acc0 = fmaf(__half2float(g_h[ssh[j] * HD + tid]), exf[j * 4 + head], acc0);
        __syncthreads();
    }
    // per-head exp-sum: warp shuffle reduce, then combine 4 warp partials
    #pragma unroll
    for (int o = 16; o; o >>= 1) {
        sum.x += __shfl_down_sync(0xffffffffu, sum.x, o);
        sum.y += __shfl_down_sync(0xffffffffu, sum.y, o);
        sum.z += __shfl_down_sync(0xffffffffu, sum.z, o);
        sum.w += __shfl_down_sync(0xffffffffu, sum.w, o);
    }
    if (lane == 0) wsum[warp] = sum;
    __syncthreads();
    float4 t0 = wsum[0], t1 = wsum[1], t2 = wsum[2], t3 = wsum[3];
    float4 tot = f4add(f4add(t0, t1), f4add(t2, t3));
    float sv = (head == 0) ? tot.x : (head == 1) ? tot.y : (head == 2) ? tot.z : tot.w;
    float inv = 1.0f / (sv + 1e-16f);
    float o   = (acc0 + acc1 + acc2 + acc3) * inv + bias[tid];
    g_x2[d * HD + tid] = fmaxf(o, 0.0f);
}

// ---------------- BatchNorm stats (apply folded downstream) ----------------
__global__ void bn_reduce(int n) {
    int c = threadIdx.x;
    float s = 0.f, q = 0.f;
    for (int r = blockIdx.x; r < n; r += gridDim.x) {
        float v = g_x2[r * HD + c];
        s += v; q += v * v;
    }
    atomicAdd(&g_bn[c], s);
    atomicAdd(&g_bn[HD + c], q);
}

__global__ void bn_final(const float* __restrict__ gamma, const float* __restrict__ beta, int n) {
    int c = threadIdx.x;
    float fn = (float)n;
    float mu  = g_bn[c] / fn;
    float var = g_bn[HD + c] / fn - mu * mu;
    float inv = rsqrtf(var + 1e-5f);
    float sc  = gamma[c] * inv;
    g_scale[c] = sc;
    g_shift[c] = beta[c] - mu * sc;
    g_bn[c] = 0.f;
    g_bn[HD + c] = 0.f;
}

// ---------------- pooling: batch sorted -> segmented register accumulation ----------------
__global__ __launch_bounds__(128) void pool_kernel(const int* __restrict__ batch, int n, int chunk) {
    int i0 = blockIdx.x * chunk;
    if (i0 >= n) return;
    int i1 = min(n, i0 + chunk);
    int t  = threadIdx.x;
    float acc = 0.f;
    int cur = batch[i0];
    int run = 0;
    for (int i = i0; i < i1; i++) {
        int g = batch[i];
        if (g != cur) {
            atomicAdd(&g_pool[cur * HD + t], acc);
            if (t == 0) atomicAdd(&g_cnt[cur], run);
            acc = 0.f; run = 0; cur = g;
        }
        acc += g_x2[i * HD + t];
        run++;
    }
    atomicAdd(&g_pool[cur * HD + t], acc);
    if (t == 0) atomicAdd(&g_cnt[cur], run);
}

// ---------------- MLP head: BN2 affine on pooled means, resets scratch ----------------
__global__ __launch_bounds__(128) void head_kernel(const float* __restrict__ L1W,
                                                   const float* __restrict__ L1b,
                                                   const float* __restrict__ L2W,
                                                   const float* __restrict__ L2b,
                                                   float* __restrict__ out) {
    int g = blockIdx.x, t = threadIdx.x;
    __shared__ float p[128], r0[128], r1[128];
    int c = g_cnt[g];
    float denom = (float)(c > 0 ? c : 1);
    p[t] = fmaf(g_pool[g * HD + t] / denom, g_scale[t], g_shift[t]);
    g_pool[g * HD + t] = 0.f;
    if (t == 0) g_cnt[g] = 0;
    __syncthreads();
    float acc = L1b[t];
    #pragma unroll 8
    for (int k = 0; k < 128; k++)
        acc = fmaf(p[k], L1W[k * HD + t], acc);
    float z = fmaxf(acc, 0.f);
    r0[t] = z * L2W[t * 2 + 0];
    r1[t] = z * L2W[t * 2 + 1];
    __syncthreads();
    for (int o = 64; o; o >>= 1) {
        if (t < o) { r0[t] += r0[t + o]; r1[t] += r1[t + o]; }
        __syncthreads();
    }
    if (t == 0) {
        out[g * 2 + 0] = r0[0] + L2b[0];
        out[g * 2 + 1] = r1[0] + L2b[1];
    }
}

// ---------------- launch ----------------
extern "C" void kernel_launch(void* const* d_in, const int* in_sizes, int n_in,
                              void* d_out, int out_size) {
    const float* x    = (const float*)d_in[0];
    const int*   ei   = (const int*)  d_in[1];
    const int*   batch= (const int*)  d_in[2];
    const float* W1   = (const float*)d_in[3];
    const float* a1s  = (const float*)d_in[4];
    const float* a1d  = (const float*)d_in[5];
    const float* b1   = (const float*)d_in[6];
    const float* bn1g = (const float*)d_in[7];
    const float* bn1b = (const float*)d_in[8];
    const float* W2   = (const float*)d_in[9];
    const float* a2s  = (const float*)d_in[10];
    const float* a2d  = (const float*)d_in[11];
    const float* b2   = (const float*)d_in[12];
    const float* bn2g = (const float*)d_in[13];
    const float* bn2b = (const float*)d_in[14];
    const float* L1W  = (const float*)d_in[15];
    const float* L1b  = (const float*)d_in[16];
    const float* L2W  = (const float*)d_in[17];
    const float* L2b  = (const float*)d_in[18];

    int n = in_sizes[0] / HD;
    int E = in_sizes[1] / 2;
    int G = out_size / 2;
    int ET = E + n;

    zero_prep   <<<(n  + 255) / 256, 256>>>(n);
    count_kernel<<<(ET + 255) / 256, 256>>>(ei, E, n);
    scan_kernel <<<1, 1024>>>(n);
    fill_kernel <<<(ET + 255) / 256, 256>>>(ei, E, n);

    int gb = (n + 127) / 128;

    gemm128<<<gb, 256>>>(x, W1, n, 0, 0, a1s, a1d);
    gat_agg<<<n, 128>>>(b1);
    bn_reduce<<<512, 128>>>(n);
    bn_final <<<1, 128>>>(bn1g, bn1b, n);

    gemm128<<<gb, 256>>>(nullptr, W2, n, 1, 1, a2s, a2d);
    gat_agg<<<n, 128>>>(b2);
    bn_reduce<<<512, 128>>>(n);
    bn_final <<<1, 128>>>(bn2g, bn2b, n);

    pool_kernel<<<(n + 255) / 256, 128>>>(batch, n, 256);
    head_kernel<<<G, 128>>>(L1W, L1b, L2W, L2b, (float*)d_out);
}

// round 5
// speedup vs baseline: 1.2188x; 1.0331x over previous
#include <cuda_runtime.h>
#include <cuda_fp16.h>
#include <math.h>

#define DIN 128
#define HD  128
#define NH  4
#define NMAX 50000
#define ET_MAX 1700000   // E + N self loops
#define GMAX 256

// ---------------- scratch (static device globals; no allocation) ----------------
__device__ __half g_h [NMAX * HD];    // GEMM output (pre-attention features), fp16 payload
__device__ float g_x2[NMAX * HD];     // layer output / next layer input
__device__ float g_as[NMAX * NH];
__device__ float g_ad[NMAX * NH];
__device__ int   g_deg[NMAX];
__device__ int   g_off[NMAX + 1];
__device__ int   g_cur[NMAX];
__device__ int   g_csr[ET_MAX];
__device__ float g_bn[2 * HD];        // col sum, col sumsq (zero-init, reset by bn_final)
__device__ float g_scale[HD];
__device__ float g_shift[HD];
__device__ float g_pool[GMAX * HD];   // zero-init, reset by head kernel
__device__ int   g_cnt[GMAX];

// ---------------- helpers ----------------
__device__ __forceinline__ float4 f4add(float4 a, float4 b) {
    return make_float4(a.x + b.x, a.y + b.y, a.z + b.z, a.w + b.w);
}
__device__ __forceinline__ float4 f4lrelu(float4 v) {
    return make_float4(fmaxf(v.x, 0.2f * v.x), fmaxf(v.y, 0.2f * v.y),
                       fmaxf(v.z, 0.2f * v.z), fmaxf(v.w, 0.2f * v.w));
}
__device__ __forceinline__ unsigned h2_as_u32(__half2 h) {
    return *reinterpret_cast<unsigned*>(&h);
}

// ---------------- CSR build ----------------
__global__ void zero_prep(int n) {
    int i = blockIdx.x * blockDim.x + threadIdx.x;
    if (i < n) { g_deg[i] = 0; g_cur[i] = 0; }
}

__global__ void count_kernel(const int* __restrict__ ei, int E, int n) {
    int i = blockIdx.x * blockDim.x + threadIdx.x;
    if (i >= E + n) return;
    int d = (i < E) ? ei[E + i] : (i - E);
    atomicAdd(&g_deg[d], 1);
}

// single-block exclusive scan of g_deg -> g_off
__global__ void scan_kernel(int n) {
    __shared__ int warp_sums[32];
    __shared__ int carry_sh;
    int t = threadIdx.x;
    int lane = t & 31, wid = t >> 5;
    if (t == 0) { carry_sh = 0; g_off[0] = 0; }
    __syncthreads();
    for (int base = 0; base < n; base += 1024) {
        int i = base + t;
        int v = (i < n) ? g_deg[i] : 0;
        int x = v;
        #pragma unroll
        for (int o = 1; o < 32; o <<= 1) {
            int y = __shfl_up_sync(0xffffffffu, x, o);
            if (lane >= o) x += y;
        }
        if (lane == 31) warp_sums[wid] = x;
        __syncthreads();
        if (wid == 0) {
            int w = warp_sums[lane];
            #pragma unroll
            for (int o = 1; o < 32; o <<= 1) {
                int y = __shfl_up_sync(0xffffffffu, w, o);
                if (lane >= o) w += y;
            }
            warp_sums[lane] = w;
        }
        __syncthreads();
        int warp_off = (wid > 0) ? warp_sums[wid - 1] : 0;
        int incl = carry_sh + warp_off + x;
        if (i < n) g_off[i + 1] = incl;
        __syncthreads();
        if (t == 1023) carry_sh = incl;
        __syncthreads();
    }
}

__global__ void fill_kernel(const int* __restrict__ ei, int E, int n) {
    int i = blockIdx.x * blockDim.x + threadIdx.x;
    if (i >= E + n) return;
    int s, d;
    if (i < E) { s = ei[i]; d = ei[E + i]; }
    else       { s = d = i - E; }
    int pos = g_off[d] + atomicAdd(&g_cur[d], 1);
    g_csr[pos] = s;
}

// ---------------- GEMM: g_h[M,128](fp16) = A[M,128] @ B[128,128], fused:
//   - optional per-column affine on A (folded BatchNorm)
//   - fused attention logits g_as/g_ad (dot with a_src/a_dst per head, fp32 acc)
__global__ __launch_bounds__(256) void gemm128(const float* __restrict__ Ain,
                                               const float* __restrict__ B,
                                               int M, int use_x2, int use_scale,
                                               const float* __restrict__ a_src,
                                               const float* __restrict__ a_dst) {
    const float* A = use_x2 ? (const float*)g_x2 : Ain;
    __shared__ float As[16][132];
    __shared__ float Bs[16][128];
    __shared__ float sA[128][NH];
    __shared__ float sD[128][NH];
    int tid  = threadIdx.x;
    int row0 = blockIdx.x * 128;
    int tm = (tid >> 4) * 8;
    int tn = (tid & 15) * 8;

    #pragma unroll
    for (int l = 0; l < 2; l++) {
        int idx = tid * 2 + l;
        sA[idx >> 2][idx & 3] = 0.f;
        sD[idx >> 2][idx & 3] = 0.f;
    }

    float acc[8][8];
    #pragma unroll
    for (int i = 0; i < 8; i++)
        #pragma unroll
        for (int j = 0; j < 8; j++) acc[i][j] = 0.f;

    for (int k0 = 0; k0 < 128; k0 += 16) {
        #pragma unroll
        for (int l = 0; l < 2; l++) {
            int slot = tid * 2 + l;
            int r  = slot >> 2;
            int kq = slot & 3;
            float4 v = make_float4(0.f, 0.f, 0.f, 0.f);
            int grow = row0 + r;
            if (grow < M) {
                v = *(const float4*)(A + grow * 128 + k0 + kq * 4);
                if (use_scale) {
                    float4 sc = *(const float4*)(g_scale + k0 + kq * 4);
                    float4 sf = *(const float4*)(g_shift + k0 + kq * 4);
                    v.x = fmaf(v.x, sc.x, sf.x);
                    v.y = fmaf(v.y, sc.y, sf.y);
                    v.z = fmaf(v.z, sc.z, sf.z);
                    v.w = fmaf(v.w, sc.w, sf.w);
                }
            }
            As[kq * 4 + 0][r] = v.x;
            As[kq * 4 + 1][r] = v.y;
            As[kq * 4 + 2][r] = v.z;
            As[kq * 4 + 3][r] = v.w;
        }
        #pragma unroll
        for (int l = 0; l < 2; l++) {
            int slot = tid * 2 + l;
            int kr = slot >> 5;
            int cq = slot & 31;
            *(float4*)(&Bs[kr][cq * 4]) = *(const float4*)(B + (k0 + kr) * 128 + cq * 4);
        }
        __syncthreads();
        #pragma unroll
        for (int kk = 0; kk < 16; kk++) {
            float a[8], b[8];
            *(float4*)(a)     = *(float4*)(&As[kk][tm]);
            *(float4*)(a + 4) = *(float4*)(&As[kk][tm + 4]);
            *(float4*)(b)     = *(float4*)(&Bs[kk][tn]);
            *(float4*)(b + 4) = *(float4*)(&Bs[kk][tn + 4]);
            #pragma unroll
            for (int i = 0; i < 8; i++)
                #pragma unroll
                for (int j = 0; j < 8; j++)
                    acc[i][j] = fmaf(a[i], b[j], acc[i][j]);
        }
        __syncthreads();
    }

    // epilogue: fp16 store + fused per-head attention logit partials (fp32)
    float asv[8], adv[8];
    #pragma unroll
    for (int j = 0; j < 8; j++) { asv[j] = a_src[tn + j]; adv[j] = a_dst[tn + j]; }
    int head = tn >> 5;
    #pragma unroll
    for (int i = 0; i < 8; i++) {
        int r = row0 + tm + i;
        float ps = 0.f, pd = 0.f;
        #pragma unroll
        for (int j = 0; j < 8; j++) {
            ps = fmaf(acc[i][j], asv[j], ps);
            pd = fmaf(acc[i][j], adv[j], pd);
        }
        if (r < M) {
            uint4 pk;
            pk.x = h2_as_u32(__floats2half2_rn(acc[i][0], acc[i][1]));
            pk.y = h2_as_u32(__floats2half2_rn(acc[i][2], acc[i][3]));
            pk.z = h2_as_u32(__floats2half2_rn(acc[i][4], acc[i][5]));
            pk.w = h2_as_u32(__floats2half2_rn(acc[i][6], acc[i][7]));
            *(uint4*)(&g_h[r * 128 + tn]) = pk;
            atomicAdd(&sA[tm + i][head], ps);
            atomicAdd(&sD[tm + i][head], pd);
        }
    }
    __syncthreads();
    #pragma unroll
    for (int l = 0; l < 2; l++) {
        int idx = tid * 2 + l;
        int r = idx >> 2, h = idx & 3;
        if (row0 + r < M) {
            g_as[(row0 + r) * NH + h] = sA[r][h];
            g_ad[(row0 + r) * NH + h] = sD[r][h];
        }
    }
}

// ---------------- GAT aggregation: one block per dst node ----------------
// Thread t = e8*16 + c16: edge-slot e8 (0..7), 8-column group c16 (0..15).
// Per inner iteration: 1 LDG.128 (8 fp16 cols), 1 LDS idx, 1 LDS weight, 8 FMA.
__global__ __launch_bounds__(128) void gat_agg(const float* __restrict__ bias) {
    int d    = blockIdx.x;
    int tid  = threadIdx.x;
    int lane = tid & 31;
    int warp = tid >> 5;
    int e8   = tid >> 4;        // 0..7 edge slot
    int c16  = tid & 15;        // 0..15 column group
    int head = c16 >> 2;        // 0..3 (8 cols all within one 32-col head)

    __shared__ float4 sh4[128];      // staged per-edge head-exps
    __shared__ int    ssh[128];      // staged src indices
    __shared__ float4 wsum[4];
    __shared__ float  sacc[8 * 136]; // slot-reduction scratch, padded

    int beg = g_off[d];
    int deg = g_off[d + 1] - beg;
    float4 adv = ((const float4*)g_ad)[d];

    float4 sum = make_float4(0.f, 0.f, 0.f, 0.f);
    float acc[8];
    #pragma unroll
    for (int i = 0; i < 8; i++) acc[i] = 0.f;

    for (int base = 0; base < deg; base += 128) {
        int k = base + tid;
        if (k < deg) {
            int s = g_csr[beg + k];
            float4 e = f4lrelu(f4add(((const float4*)g_as)[s], adv));
            float4 ex = make_float4(__expf(e.x), __expf(e.y), __expf(e.z), __expf(e.w));
            sum = f4add(sum, ex);
            sh4[tid] = ex;
            ssh[tid] = s;
        }
        __syncthreads();
        int cnt = min(128, deg - base);
        const float* exf = (const float*)sh4;
        for (int j = e8; j < cnt; j += 8) {
            int   s = ssh[j];
            float w = exf[j * 4 + head];
            uint4 pk = *(const uint4*)(&g_h[s * HD + c16 * 8]);
            __half2* hp = reinterpret_cast<__half2*>(&pk);
            float2 f0 = __half22float2(hp[0]);
            float2 f1 = __half22float2(hp[1]);
            float2 f2 = __half22float2(hp[2]);
            float2 f3 = __half22float2(hp[3]);
            acc[0] = fmaf(f0.x, w, acc[0]);
            acc[1] = fmaf(f0.y, w, acc[1]);
            acc[2] = fmaf(f1.x, w, acc[2]);
            acc[3] = fmaf(f1.y, w, acc[3]);
            acc[4] = fmaf(f2.x, w, acc[4]);
            acc[5] = fmaf(f2.y, w, acc[5]);
            acc[6] = fmaf(f3.x, w, acc[6]);
            acc[7] = fmaf(f3.y, w, acc[7]);
        }
        __syncthreads();
    }

    // per-head exp-sum: warp shuffle reduce, then combine 4 warp partials
    #pragma unroll
    for (int o = 16; o; o >>= 1) {
        sum.x += __shfl_down_sync(0xffffffffu, sum.x, o);
        sum.y += __shfl_down_sync(0xffffffffu, sum.y, o);
        sum.z += __shfl_down_sync(0xffffffffu, sum.z, o);
        sum.w += __shfl_down_sync(0xffffffffu, sum.w, o);
    }
    if (lane == 0) wsum[warp] = sum;

    // fold the 8 edge slots: sacc[e8][c16*8 + k], padded stride 136
    float* my = &sacc[e8 * 136 + c16 * 8];
    *(float4*)(my)     = make_float4(acc[0], acc[1], acc[2], acc[3]);
    *(float4*)(my + 4) = make_float4(acc[4], acc[5], acc[6], acc[7]);
    __syncthreads();
    #pragma unroll
    for (int o = 4; o; o >>= 1) {
        if (e8 < o) {
            const float* other = &sacc[(e8 + o) * 136 + c16 * 8];
            float4 a0 = *(float4*)(my);
            float4 a1 = *(float4*)(my + 4);
            float4 b0 = *(const float4*)(other);
            float4 b1 = *(const float4*)(other + 4);
            *(float4*)(my)     = f4add(a0, b0);
            *(float4*)(my + 4) = f4add(a1, b1);
        }
        __syncthreads();
    }

    if (e8 == 0) {
        float4 t0 = wsum[0], t1 = wsum[1], t2 = wsum[2], t3 = wsum[3];
        float4 tot = f4add(f4add(t0, t1), f4add(t2, t3));
        float sv = (head == 0) ? tot.x : (head == 1) ? tot.y : (head == 2) ? tot.z : tot.w;
        float inv = 1.0f / (sv + 1e-16f);
        float4 r0 = *(float4*)(my);
        float4 r1 = *(float4*)(my + 4);
        const float* bp = bias + c16 * 8;
        float4 b0 = *(const float4*)(bp);
        float4 b1 = *(const float4*)(bp + 4);
        float4 o0 = make_float4(fmaxf(fmaf(r0.x, inv, b0.x), 0.f),
                                fmaxf(fmaf(r0.y, inv, b0.y), 0.f),
                                fmaxf(fmaf(r0.z, inv, b0.z), 0.f),
                                fmaxf(fmaf(r0.w, inv, b0.w), 0.f));
        float4 o1 = make_float4(fmaxf(fmaf(r1.x, inv, b1.x), 0.f),
                                fmaxf(fmaf(r1.y, inv, b1.y), 0.f),
                                fmaxf(fmaf(r1.z, inv, b1.z), 0.f),
                                fmaxf(fmaf(r1.w, inv, b1.w), 0.f));
        *(float4*)(&g_x2[d * HD + c16 * 8])     = o0;
        *(float4*)(&g_x2[d * HD + c16 * 8 + 4]) = o1;
    }
}

// ---------------- BatchNorm stats (apply folded downstream) ----------------
__global__ void bn_reduce(int n) {
    int c = threadIdx.x;
    float s = 0.f, q = 0.f;
    for (int r = blockIdx.x; r < n; r += gridDim.x) {
        float v = g_x2[r * HD + c];
        s += v; q += v * v;
    }
    atomicAdd(&g_bn[c], s);
    atomicAdd(&g_bn[HD + c], q);
}

__global__ void bn_final(const float* __restrict__ gamma, const float* __restrict__ beta, int n) {
    int c = threadIdx.x;
    float fn = (float)n;
    float mu  = g_bn[c] / fn;
    float var = g_bn[HD + c] / fn - mu * mu;
    float inv = rsqrtf(var + 1e-5f);
    float sc  = gamma[c] * inv;
    g_scale[c] = sc;
    g_shift[c] = beta[c] - mu * sc;
    g_bn[c] = 0.f;
    g_bn[HD + c] = 0.f;
}

// ---------------- pooling: batch sorted -> segmented register accumulation ----------------
__global__ __launch_bounds__(128) void pool_kernel(const int* __restrict__ batch, int n, int chunk) {
    int i0 = blockIdx.x * chunk;
    if (i0 >= n) return;
    int i1 = min(n, i0 + chunk);
    int t  = threadIdx.x;
    float acc = 0.f;
    int cur = batch[i0];
    int run = 0;
    for (int i = i0; i < i1; i++) {
        int g = batch[i];
        if (g != cur) {
            atomicAdd(&g_pool[cur * HD + t], acc);
            if (t == 0) atomicAdd(&g_cnt[cur], run);
            acc = 0.f; run = 0; cur = g;
        }
        acc += g_x2[i * HD + t];
        run++;
    }
    atomicAdd(&g_pool[cur * HD + t], acc);
    if (t == 0) atomicAdd(&g_cnt[cur], run);
}

// ---------------- MLP head: BN2 affine on pooled means, resets scratch ----------------
__global__ __launch_bounds__(128) void head_kernel(const float* __restrict__ L1W,
                                                   const float* __restrict__ L1b,
                                                   const float* __restrict__ L2W,
                                                   const float* __restrict__ L2b,
                                                   float* __restrict__ out) {
    int g = blockIdx.x, t = threadIdx.x;
    __shared__ float p[128], r0[128], r1[128];
    int c = g_cnt[g];
    float denom = (float)(c > 0 ? c : 1);
    p[t] = fmaf(g_pool[g * HD + t] / denom, g_scale[t], g_shift[t]);
    g_pool[g * HD + t] = 0.f;
    if (t == 0) g_cnt[g] = 0;
    __syncthreads();
    float acc = L1b[t];
    #pragma unroll 8
    for (int k = 0; k < 128; k++)
        acc = fmaf(p[k], L1W[k * HD + t], acc);
    float z = fmaxf(acc, 0.f);
    r0[t] = z * L2W[t * 2 + 0];
    r1[t] = z * L2W[t * 2 + 1];
    __syncthreads();
    for (int o = 64; o; o >>= 1) {
        if (t < o) { r0[t] += r0[t + o]; r1[t] += r1[t + o]; }
        __syncthreads();
    }
    if (t == 0) {
        out[g * 2 + 0] = r0[0] + L2b[0];
        out[g * 2 + 1] = r1[0] + L2b[1];
    }
}

// ---------------- launch ----------------
extern "C" void kernel_launch(void* const* d_in, const int* in_sizes, int n_in,
                              void* d_out, int out_size) {
    const float* x    = (const float*)d_in[0];
    const int*   ei   = (const int*)  d_in[1];
    const int*   batch= (const int*)  d_in[2];
    const float* W1   = (const float*)d_in[3];
    const float* a1s  = (const float*)d_in[4];
    const float* a1d  = (const float*)d_in[5];
    const float* b1   = (const float*)d_in[6];
    const float* bn1g = (const float*)d_in[7];
    const float* bn1b = (const float*)d_in[8];
    const float* W2   = (const float*)d_in[9];
    const float* a2s  = (const float*)d_in[10];
    const float* a2d  = (const float*)d_in[11];
    const float* b2   = (const float*)d_in[12];
    const float* bn2g = (const float*)d_in[13];
    const float* bn2b = (const float*)d_in[14];
    const float* L1W  = (const float*)d_in[15];
    const float* L1b  = (const float*)d_in[16];
    const float* L2W  = (const float*)d_in[17];
    const float* L2b  = (const float*)d_in[18];

    int n = in_sizes[0] / HD;
    int E = in_sizes[1] / 2;
    int G = out_size / 2;
    int ET = E + n;

    zero_prep   <<<(n  + 255) / 256, 256>>>(n);
    count_kernel<<<(ET + 255) / 256, 256>>>(ei, E, n);
    scan_kernel <<<1, 1024>>>(n);
    fill_kernel <<<(ET + 255) / 256, 256>>>(ei, E, n);

    int gb = (n + 127) / 128;

    gemm128<<<gb, 256>>>(x, W1, n, 0, 0, a1s, a1d);
    gat_agg<<<n, 128>>>(b1);
    bn_reduce<<<512, 128>>>(n);
    bn_final <<<1, 128>>>(bn1g, bn1b, n);

    gemm128<<<gb, 256>>>(nullptr, W2, n, 1, 1, a2s, a2d);
    gat_agg<<<n, 128>>>(b2);
    bn_reduce<<<512, 128>>>(n);
    bn_final <<<1, 128>>>(bn2g, bn2b, n);

    pool_kernel<<<(n + 255) / 256, 128>>>(batch, n, 256);
    head_kernel<<<G, 128>>>(L1W, L1b, L2W, L2b, (float*)d_out);
}

// round 6
// speedup vs baseline: 1.5505x; 1.2722x over previous
#include <cuda_runtime.h>
#include <cuda_fp16.h>
#include <math.h>

#define DIN 128
#define HD  128
#define NH  4
#define NMAX 50000
#define ET_MAX 1700000   // E + N self loops
#define GMAX 256

// ---------------- scratch (static device globals; no allocation) ----------------
__device__ __half g_h [NMAX * HD];    // GEMM output (pre-attention features), fp16 payload
__device__ float g_x2[NMAX * HD];     // layer output / next layer input
__device__ float g_as[NMAX * NH];
__device__ float g_ad[NMAX * NH];
__device__ int   g_deg[NMAX];
__device__ int   g_off[NMAX + 1];
__device__ int   g_cur[NMAX];
__device__ int   g_csr[ET_MAX];
__device__ float g_bn[2 * HD];        // col sum, col sumsq (zero-init, reset by bn_final)
__device__ float g_scale[HD];
__device__ float g_shift[HD];
__device__ float g_pool[GMAX * HD];   // zero-init, reset by head kernel
__device__ int   g_cnt[GMAX];

// ---------------- helpers ----------------
__device__ __forceinline__ float4 f4add(float4 a, float4 b) {
    return make_float4(a.x + b.x, a.y + b.y, a.z + b.z, a.w + b.w);
}
__device__ __forceinline__ float4 f4lrelu(float4 v) {
    return make_float4(fmaxf(v.x, 0.2f * v.x), fmaxf(v.y, 0.2f * v.y),
                       fmaxf(v.z, 0.2f * v.z), fmaxf(v.w, 0.2f * v.w));
}
__device__ __forceinline__ unsigned h2_as_u32(__half2 h) {
    return *reinterpret_cast<unsigned*>(&h);
}

// ---------------- CSR build ----------------
__global__ void count_kernel(const int* __restrict__ ei, int E, int n) {
    int i = blockIdx.x * blockDim.x + threadIdx.x;
    if (i >= E + n) return;
    int d = (i < E) ? ei[E + i] : (i - E);
    atomicAdd(&g_deg[d], 1);
}

// single-block exclusive scan of g_deg -> g_off, 4 elems/thread.
// Also zeroes g_deg (for next call) and g_cur (for fill later this call).
__global__ void scan_kernel(int n) {
    __shared__ int warp_sums[32];
    __shared__ int carry_sh;
    int t = threadIdx.x;
    int lane = t & 31, wid = t >> 5;
    if (t == 0) { carry_sh = 0; g_off[0] = 0; }
    __syncthreads();
    for (int base = 0; base < n; base += 4096) {
        int i = base + t * 4;
        int v0 = 0, v1 = 0, v2 = 0, v3 = 0;
        if (i + 3 < n) {
            int4 v = *(const int4*)&g_deg[i];
            v0 = v.x; v1 = v.y; v2 = v.z; v3 = v.w;
        } else {
            if (i     < n) v0 = g_deg[i];
            if (i + 1 < n) v1 = g_deg[i + 1];
            if (i + 2 < n) v2 = g_deg[i + 2];
            if (i + 3 < n) v3 = g_deg[i + 3];
        }
        int p0 = v0, p1 = p0 + v1, p2 = p1 + v2, p3 = p2 + v3;
        int x = p3;
        #pragma unroll
        for (int o = 1; o < 32; o <<= 1) {
            int y = __shfl_up_sync(0xffffffffu, x, o);
            if (lane >= o) x += y;
        }
        if (lane == 31) warp_sums[wid] = x;
        __syncthreads();
        if (wid == 0) {
            int w = warp_sums[lane];
            #pragma unroll
            for (int o = 1; o < 32; o <<= 1) {
                int y = __shfl_up_sync(0xffffffffu, w, o);
                if (lane >= o) w += y;
            }
            warp_sums[lane] = w;
        }
        __syncthreads();
        int woff = (wid > 0) ? warp_sums[wid - 1] : 0;
        int excl = carry_sh + woff + (x - p3);
        if (i     < n) g_off[i + 1] = excl + p0;
        if (i + 1 < n) g_off[i + 2] = excl + p1;
        if (i + 2 < n) g_off[i + 3] = excl + p2;
        if (i + 3 < n) g_off[i + 4] = excl + p3;
        // zero for next call / for fill
        int4 z4 = make_int4(0, 0, 0, 0);
        if (i + 3 < n) {
            *(int4*)&g_deg[i] = z4;
            *(int4*)&g_cur[i] = z4;
        } else {
            for (int q = 0; q < 4; q++)
                if (i + q < n) { g_deg[i + q] = 0; g_cur[i + q] = 0; }
        }
        __syncthreads();
        if (t == 1023) carry_sh = excl + p3;
        __syncthreads();
    }
}

__global__ void fill_kernel(const int* __restrict__ ei, int E, int n) {
    int i = blockIdx.x * blockDim.x + threadIdx.x;
    if (i >= E + n) return;
    int s, d;
    if (i < E) { s = ei[i]; d = ei[E + i]; }
    else       { s = d = i - E; }
    int pos = g_off[d] + atomicAdd(&g_cur[d], 1);
    g_csr[pos] = s;
}

// ---------------- GEMM: g_h[M,128](fp16) = A[M,128] @ B[128,128], fused:
//   - optional per-column affine on A (folded BatchNorm)
//   - fused attention logits g_as/g_ad (dot with a_src/a_dst per head, fp32 acc)
__global__ __launch_bounds__(256) void gemm128(const float* __restrict__ Ain,
                                               const float* __restrict__ B,
                                               int M, int use_x2, int use_scale,
                                               const float* __restrict__ a_src,
                                               const float* __restrict__ a_dst) {
    const float* A = use_x2 ? (const float*)g_x2 : Ain;
    __shared__ float As[16][132];
    __shared__ float Bs[16][128];
    __shared__ float sA[128][NH];
    __shared__ float sD[128][NH];
    int tid  = threadIdx.x;
    int row0 = blockIdx.x * 128;
    int tm = (tid >> 4) * 8;
    int tn = (tid & 15) * 8;

    #pragma unroll
    for (int l = 0; l < 2; l++) {
        int idx = tid * 2 + l;
        sA[idx >> 2][idx & 3] = 0.f;
        sD[idx >> 2][idx & 3] = 0.f;
    }

    float acc[8][8];
    #pragma unroll
    for (int i = 0; i < 8; i++)
        #pragma unroll
        for (int j = 0; j < 8; j++) acc[i][j] = 0.f;

    for (int k0 = 0; k0 < 128; k0 += 16) {
        #pragma unroll
        for (int l = 0; l < 2; l++) {
            int slot = tid * 2 + l;
            int r  = slot >> 2;
            int kq = slot & 3;
            float4 v = make_float4(0.f, 0.f, 0.f, 0.f);
            int grow = row0 + r;
            if (grow < M) {
                v = *(const float4*)(A + grow * 128 + k0 + kq * 4);
                if (use_scale) {
                    float4 sc = *(const float4*)(g_scale + k0 + kq * 4);
                    float4 sf = *(const float4*)(g_shift + k0 + kq * 4);
                    v.x = fmaf(v.x, sc.x, sf.x);
                    v.y = fmaf(v.y, sc.y, sf.y);
                    v.z = fmaf(v.z, sc.z, sf.z);
                    v.w = fmaf(v.w, sc.w, sf.w);
                }
            }
            As[kq * 4 + 0][r] = v.x;
            As[kq * 4 + 1][r] = v.y;
            As[kq * 4 + 2][r] = v.z;
            As[kq * 4 + 3][r] = v.w;
        }
        #pragma unroll
        for (int l = 0; l < 2; l++) {
            int slot = tid * 2 + l;
            int kr = slot >> 5;
            int cq = slot & 31;
            *(float4*)(&Bs[kr][cq * 4]) = *(const float4*)(B + (k0 + kr) * 128 + cq * 4);
        }
        __syncthreads();
        #pragma unroll
        for (int kk = 0; kk < 16; kk++) {
            float a[8], b[8];
            *(float4*)(a)     = *(float4*)(&As[kk][tm]);
            *(float4*)(a + 4) = *(float4*)(&As[kk][tm + 4]);
            *(float4*)(b)     = *(float4*)(&Bs[kk][tn]);
            *(float4*)(b + 4) = *(float4*)(&Bs[kk][tn + 4]);
            #pragma unroll
            for (int i = 0; i < 8; i++)
                #pragma unroll
                for (int j = 0; j < 8; j++)
                    acc[i][j] = fmaf(a[i], b[j], acc[i][j]);
        }
        __syncthreads();
    }

    float asv[8], adv[8];
    #pragma unroll
    for (int j = 0; j < 8; j++) { asv[j] = a_src[tn + j]; adv[j] = a_dst[tn + j]; }
    int head = tn >> 5;
    #pragma unroll
    for (int i = 0; i < 8; i++) {
        int r = row0 + tm + i;
        float ps = 0.f, pd = 0.f;
        #pragma unroll
        for (int j = 0; j < 8; j++) {
            ps = fmaf(acc[i][j], asv[j], ps);
            pd = fmaf(acc[i][j], adv[j], pd);
        }
        if (r < M) {
            uint4 pk;
            pk.x = h2_as_u32(__floats2half2_rn(acc[i][0], acc[i][1]));
            pk.y = h2_as_u32(__floats2half2_rn(acc[i][2], acc[i][3]));
            pk.z = h2_as_u32(__floats2half2_rn(acc[i][4], acc[i][5]));
            pk.w = h2_as_u32(__floats2half2_rn(acc[i][6], acc[i][7]));
            *(uint4*)(&g_h[r * 128 + tn]) = pk;
            atomicAdd(&sA[tm + i][head], ps);
            atomicAdd(&sD[tm + i][head], pd);
        }
    }
    __syncthreads();
    #pragma unroll
    for (int l = 0; l < 2; l++) {
        int idx = tid * 2 + l;
        int r = idx >> 2, h = idx & 3;
        if (row0 + r < M) {
            g_as[(row0 + r) * NH + h] = sA[r][h];
            g_ad[(row0 + r) * NH + h] = sD[r][h];
        }
    }
}

// ---------------- GAT aggregation: one WARP per dst node + fused BN stats ----------------
// Lane owns columns [lane*4, lane*4+4): 1 LDG.64 per edge per lane (coalesced 256B/warp).
__global__ __launch_bounds__(256) void gat_agg(const float* __restrict__ bias, int n) {
    __shared__ int   s_idx[8][32];
    __shared__ float s_ex [8][128];
    __shared__ float sbn[256];          // [0:128) col sums, [128:256) col sumsq

    int tid  = threadIdx.x;
    int w    = tid >> 5;
    int lane = tid & 31;
    int head = lane >> 3;

    sbn[tid] = 0.f;
    __syncthreads();

    int d = blockIdx.x * 8 + w;
    if (d < n) {
        int beg = g_off[d];
        int deg = g_off[d + 1] - beg;
        float4 adv = ((const float4*)g_ad)[d];

        float4 sumex = make_float4(0.f, 0.f, 0.f, 0.f);
        float acc0 = 0.f, acc1 = 0.f, acc2 = 0.f, acc3 = 0.f;

        for (int base = 0; base < deg; base += 32) {
            int k = base + lane;
            if (k < deg) {
                int s = g_csr[beg + k];
                float4 e = f4lrelu(f4add(((const float4*)g_as)[s], adv));
                float4 ex = make_float4(__expf(e.x), __expf(e.y), __expf(e.z), __expf(e.w));
                sumex = f4add(sumex, ex);
                s_idx[w][lane] = s;
                *(float4*)&s_ex[w][lane * 4] = ex;
            }
            __syncwarp();
            int cnt = min(32, deg - base);
            if (cnt == 32) {
                #pragma unroll 8
                for (int j = 0; j < 32; j++) {
                    int   s  = s_idx[w][j];
                    float wt = s_ex[w][j * 4 + head];
                    uint2 pk = *(const uint2*)(&g_h[s * HD + lane * 4]);
                    __half2* hp = reinterpret_cast<__half2*>(&pk);
                    float2 f0 = __half22float2(hp[0]);
                    float2 f1 = __half22float2(hp[1]);
                    acc0 = fmaf(f0.x, wt, acc0);
                    acc1 = fmaf(f0.y, wt, acc1);
                    acc2 = fmaf(f1.x, wt, acc2);
                    acc3 = fmaf(f1.y, wt, acc3);
                }
            } else {
                #pragma unroll 4
                for (int j = 0; j < cnt; j++) {
                    int   s  = s_idx[w][j];
                    float wt = s_ex[w][j * 4 + head];
                    uint2 pk = *(const uint2*)(&g_h[s * HD + lane * 4]);
                    __half2* hp = reinterpret_cast<__half2*>(&pk);
                    float2 f0 = __half22float2(hp[0]);
                    float2 f1 = __half22float2(hp[1]);
                    acc0 = fmaf(f0.x, wt, acc0);
                    acc1 = fmaf(f0.y, wt, acc1);
                    acc2 = fmaf(f1.x, wt, acc2);
                    acc3 = fmaf(f1.y, wt, acc3);
                }
            }
            __syncwarp();
        }

        // warp-reduce per-head exp sums
        #pragma unroll
        for (int o = 16; o; o >>= 1) {
            sumex.x += __shfl_xor_sync(0xffffffffu, sumex.x, o);
            sumex.y += __shfl_xor_sync(0xffffffffu, sumex.y, o);
            sumex.z += __shfl_xor_sync(0xffffffffu, sumex.z, o);
            sumex.w += __shfl_xor_sync(0xffffffffu, sumex.w, o);
        }
        float sv = (head == 0) ? sumex.x : (head == 1) ? sumex.y
                 : (head == 2) ? sumex.z : sumex.w;
        float inv = 1.0f / (sv + 1e-16f);

        float4 b = *(const float4*)(bias + lane * 4);
        float o0 = fmaxf(fmaf(acc0, inv, b.x), 0.f);
        float o1 = fmaxf(fmaf(acc1, inv, b.y), 0.f);
        float o2 = fmaxf(fmaf(acc2, inv, b.z), 0.f);
        float o3 = fmaxf(fmaf(acc3, inv, b.w), 0.f);
        *(float4*)(&g_x2[d * HD + lane * 4]) = make_float4(o0, o1, o2, o3);

        // fused BN stats (block-shared, flushed once per block)
        int c = lane * 4;
        atomicAdd(&sbn[c + 0], o0);
        atomicAdd(&sbn[c + 1], o1);
        atomicAdd(&sbn[c + 2], o2);
        atomicAdd(&sbn[c + 3], o3);
        atomicAdd(&sbn[128 + c + 0], o0 * o0);
        atomicAdd(&sbn[128 + c + 1], o1 * o1);
        atomicAdd(&sbn[128 + c + 2], o2 * o2);
        atomicAdd(&sbn[128 + c + 3], o3 * o3);
    }
    __syncthreads();
    atomicAdd(&g_bn[tid], sbn[tid]);
}

// ---------------- BN finalize: scale/shift, resets g_bn ----------------
__global__ void bn_final(const float* __restrict__ gamma, const float* __restrict__ beta, int n) {
    int c = threadIdx.x;
    float fn = (float)n;
    float mu  = g_bn[c] / fn;
    float var = g_bn[HD + c] / fn - mu * mu;
    float inv = rsqrtf(var + 1e-5f);
    float sc  = gamma[c] * inv;
    g_scale[c] = sc;
    g_shift[c] = beta[c] - mu * sc;
    g_bn[c] = 0.f;
    g_bn[HD + c] = 0.f;
}

// ---------------- pooling: batch sorted -> segmented register accumulation ----------------
__global__ __launch_bounds__(128) void pool_kernel(const int* __restrict__ batch, int n, int chunk) {
    int i0 = blockIdx.x * chunk;
    if (i0 >= n) return;
    int i1 = min(n, i0 + chunk);
    int t  = threadIdx.x;
    float acc = 0.f;
    int cur = batch[i0];
    int run = 0;
    for (int i = i0; i < i1; i++) {
        int g = batch[i];
        if (g != cur) {
            atomicAdd(&g_pool[cur * HD + t], acc);
            if (t == 0) atomicAdd(&g_cnt[cur], run);
            acc = 0.f; run = 0; cur = g;
        }
        acc += g_x2[i * HD + t];
        run++;
    }
    atomicAdd(&g_pool[cur * HD + t], acc);
    if (t == 0) atomicAdd(&g_cnt[cur], run);
}

// ---------------- MLP head: BN2 affine on pooled means, resets scratch ----------------
__global__ __launch_bounds__(128) void head_kernel(const float* __restrict__ L1W,
                                                   const float* __restrict__ L1b,
                                                   const float* __restrict__ L2W,
                                                   const float* __restrict__ L2b,
                                                   float* __restrict__ out) {
    int g = blockIdx.x, t = threadIdx.x;
    __shared__ float p[128], r0[128], r1[128];
    int c = g_cnt[g];
    float denom = (float)(c > 0 ? c : 1);
    p[t] = fmaf(g_pool[g * HD + t] / denom, g_scale[t], g_shift[t]);
    g_pool[g * HD + t] = 0.f;
    if (t == 0) g_cnt[g] = 0;
    __syncthreads();
    float acc = L1b[t];
    #pragma unroll 8
    for (int k = 0; k < 128; k++)
        acc = fmaf(p[k], L1W[k * HD + t], acc);
    float z = fmaxf(acc, 0.f);
    r0[t] = z * L2W[t * 2 + 0];
    r1[t] = z * L2W[t * 2 + 1];
    __syncthreads();
    for (int o = 64; o; o >>= 1) {
        if (t < o) { r0[t] += r0[t + o]; r1[t] += r1[t + o]; }
        __syncthreads();
    }
    if (t == 0) {
        out[g * 2 + 0] = r0[0] + L2b[0];
        out[g * 2 + 1] = r1[0] + L2b[1];
    }
}

// ---------------- launch ----------------
extern "C" void kernel_launch(void* const* d_in, const int* in_sizes, int n_in,
                              void* d_out, int out_size) {
    const float* x    = (const float*)d_in[0];
    const int*   ei   = (const int*)  d_in[1];
    const int*   batch= (const int*)  d_in[2];
    const float* W1   = (const float*)d_in[3];
    const float* a1s  = (const float*)d_in[4];
    const float* a1d  = (const float*)d_in[5];
    const float* b1   = (const float*)d_in[6];
    const float* bn1g = (const float*)d_in[7];
    const float* bn1b = (const float*)d_in[8];
    const float* W2   = (const float*)d_in[9];
    const float* a2s  = (const float*)d_in[10];
    const float* a2d  = (const float*)d_in[11];
    const float* b2   = (const float*)d_in[12];
    const float* bn2g = (const float*)d_in[13];
    const float* bn2b = (const float*)d_in[14];
    const float* L1W  = (const float*)d_in[15];
    const float* L1b  = (const float*)d_in[16];
    const float* L2W  = (const float*)d_in[17];
    const float* L2b  = (const float*)d_in[18];

    int n = in_sizes[0] / HD;
    int E = in_sizes[1] / 2;
    int G = out_size / 2;
    int ET = E + n;

    // CSR build (g_deg/g_cur zeroed by previous call's scan; globals zero-init on load)
    count_kernel<<<(ET + 255) / 256, 256>>>(ei, E, n);
    scan_kernel <<<1, 1024>>>(n);
    fill_kernel <<<(ET + 255) / 256, 256>>>(ei, E, n);

    int gb  = (n + 127) / 128;
    int agb = (n + 7) / 8;

    gemm128<<<gb, 256>>>(x, W1, n, 0, 0, a1s, a1d);
    gat_agg<<<agb, 256>>>(b1, n);
    bn_final<<<1, 128>>>(bn1g, bn1b, n);

    gemm128<<<gb, 256>>>(nullptr, W2, n, 1, 1, a2s, a2d);
    gat_agg<<<agb, 256>>>(b2, n);
    bn_final<<<1, 128>>>(bn2g, bn2b, n);

    pool_kernel<<<(n + 255) / 256, 128>>>(batch, n, 256);
    head_kernel<<<G, 128>>>(L1W, L1b, L2W, L2b, (float*)d_out);
}

// round 7
// speedup vs baseline: 1.8641x; 1.2022x over previous
#include <cuda_runtime.h>
#include <cuda_fp16.h>
#include <math.h>

#define DIN 128
#define HD  128
#define NH  4
#define NMAX 50000
#define ET_MAX 1700000   // E + N self loops
#define GMAX 256
#define KC   32          // GEMM K-chunk in smem

// ---------------- scratch (static device globals; no allocation) ----------------
__device__ __half g_h [NMAX * HD];    // GEMM output (pre-attention features), fp16 payload
__device__ float g_x2[NMAX * HD];     // layer output / next layer input
__device__ float g_as[NMAX * NH];
__device__ float g_ad[NMAX * NH];
__device__ int   g_deg[NMAX];
__device__ int   g_off[NMAX + 1];
__device__ int   g_cur[NMAX];
__device__ int   g_csr[ET_MAX];
__device__ float g_bn[2 * HD];        // col sum, col sumsq (zero-init, reset by bn_final)
__device__ float g_scale[HD];
__device__ float g_shift[HD];
__device__ float g_pool[GMAX * HD];   // zero-init, reset by head kernel
__device__ int   g_cnt[GMAX];

// ---------------- helpers ----------------
__device__ __forceinline__ float4 f4add(float4 a, float4 b) {
    return make_float4(a.x + b.x, a.y + b.y, a.z + b.z, a.w + b.w);
}
__device__ __forceinline__ float4 f4lrelu(float4 v) {
    return make_float4(fmaxf(v.x, 0.2f * v.x), fmaxf(v.y, 0.2f * v.y),
                       fmaxf(v.z, 0.2f * v.z), fmaxf(v.w, 0.2f * v.w));
}
__device__ __forceinline__ unsigned h2_as_u32(__half2 h) {
    return *reinterpret_cast<unsigned*>(&h);
}
__device__ __forceinline__ float tf32_of(float v) {
    unsigned o;
    asm("cvt.rna.tf32.f32 %0, %1;" : "=r"(o) : "f"(v));
    return __uint_as_float(o);
}
__device__ __forceinline__ void mma_tf32(float c[4], const float a[4], float b0, float b1) {
    asm volatile(
        "mma.sync.aligned.m16n8k8.row.col.f32.tf32.tf32.f32 "
        "{%0,%1,%2,%3}, {%4,%5,%6,%7}, {%8,%9}, {%0,%1,%2,%3};"
        : "+f"(c[0]), "+f"(c[1]), "+f"(c[2]), "+f"(c[3])
        : "r"(__float_as_uint(a[0])), "r"(__float_as_uint(a[1])),
          "r"(__float_as_uint(a[2])), "r"(__float_as_uint(a[3])),
          "r"(__float_as_uint(b0)),   "r"(__float_as_uint(b1)));
}

// ---------------- CSR build ----------------
__global__ void count_kernel(const int* __restrict__ ei, int E, int n) {
    int i = blockIdx.x * blockDim.x + threadIdx.x;
    if (i >= E + n) return;
    int d = (i < E) ? ei[E + i] : (i - E);
    atomicAdd(&g_deg[d], 1);
}

// single-block exclusive scan of g_deg -> g_off, 4 elems/thread.
// Also zeroes g_deg (for next call) and g_cur (for fill later this call).
__global__ void scan_kernel(int n) {
    __shared__ int warp_sums[32];
    __shared__ int carry_sh;
    int t = threadIdx.x;
    int lane = t & 31, wid = t >> 5;
    if (t == 0) { carry_sh = 0; g_off[0] = 0; }
    __syncthreads();
    for (int base = 0; base < n; base += 4096) {
        int i = base + t * 4;
        int v0 = 0, v1 = 0, v2 = 0, v3 = 0;
        if (i + 3 < n) {
            int4 v = *(const int4*)&g_deg[i];
            v0 = v.x; v1 = v.y; v2 = v.z; v3 = v.w;
        } else {
            if (i     < n) v0 = g_deg[i];
            if (i + 1 < n) v1 = g_deg[i + 1];
            if (i + 2 < n) v2 = g_deg[i + 2];
            if (i + 3 < n) v3 = g_deg[i + 3];
        }
        int p0 = v0, p1 = p0 + v1, p2 = p1 + v2, p3 = p2 + v3;
        int x = p3;
        #pragma unroll
        for (int o = 1; o < 32; o <<= 1) {
            int y = __shfl_up_sync(0xffffffffu, x, o);
            if (lane >= o) x += y;
        }
        if (lane == 31) warp_sums[wid] = x;
        __syncthreads();
        if (wid == 0) {
            int w = warp_sums[lane];
            #pragma unroll
            for (int o = 1; o < 32; o <<= 1) {
                int y = __shfl_up_sync(0xffffffffu, w, o);
                if (lane >= o) w += y;
            }
            warp_sums[lane] = w;
        }
        __syncthreads();
        int woff = (wid > 0) ? warp_sums[wid - 1] : 0;
        int excl = carry_sh + woff + (x - p3);
        if (i     < n) g_off[i + 1] = excl + p0;
        if (i + 1 < n) g_off[i + 2] = excl + p1;
        if (i + 2 < n) g_off[i + 3] = excl + p2;
        if (i + 3 < n) g_off[i + 4] = excl + p3;
        int4 z4 = make_int4(0, 0, 0, 0);
        if (i + 3 < n) {
            *(int4*)&g_deg[i] = z4;
            *(int4*)&g_cur[i] = z4;
        } else {
            for (int q = 0; q < 4; q++)
                if (i + q < n) { g_deg[i + q] = 0; g_cur[i + q] = 0; }
        }
        __syncthreads();
        if (t == 1023) carry_sh = excl + p3;
        __syncthreads();
    }
}

__global__ void fill_kernel(const int* __restrict__ ei, int E, int n) {
    int i = blockIdx.x * blockDim.x + threadIdx.x;
    if (i >= E + n) return;
    int s, d;
    if (i < E) { s = ei[i]; d = ei[E + i]; }
    else       { s = d = i - E; }
    int pos = g_off[d] + atomicAdd(&g_cur[d], 1);
    g_csr[pos] = s;
}

// ---------------- tensor-core GEMM (tf32 mma.sync): g_h[M,128](fp16) = A @ B ----------------
// Fused: optional BN affine on A columns; per-head attention logits into g_as/g_ad.
// Block: 128 rows x 128 cols, 8 warps of 32x64. K chunked by KC=32 in smem.
__global__ __launch_bounds__(256, 2) void gemm_tc(const float* __restrict__ Ain,
                                                  const float* __restrict__ B,
                                                  int M, int use_x2, int use_scale,
                                                  const float* __restrict__ a_src,
                                                  const float* __restrict__ a_dst) {
    const float* A = use_x2 ? (const float*)g_x2 : Ain;
    __shared__ float As[128][KC + 4];   // stride 36: mma A loads conflict-free
    __shared__ float Bs[KC][132];       // [k][n], stride 132
    __shared__ float sA[128][NH];
    __shared__ float sD[128][NH];

    int tid  = threadIdx.x;
    int lane = tid & 31;
    int warp = tid >> 5;
    int warpM = warp >> 1;              // 0..3
    int warpN = warp & 1;               // 0..1
    int row0 = blockIdx.x * 128;

    #pragma unroll
    for (int l = 0; l < 2; l++) {
        int idx = tid * 2 + l;
        sA[idx >> 2][idx & 3] = 0.f;
        sD[idx >> 2][idx & 3] = 0.f;
    }

    float c[2][8][4];
    #pragma unroll
    for (int m = 0; m < 2; m++)
        #pragma unroll
        for (int j = 0; j < 8; j++)
            #pragma unroll
            for (int q = 0; q < 4; q++) c[m][j][q] = 0.f;

    for (int kc = 0; kc < 128; kc += KC) {
        // stage A chunk: 128 x 32 floats = 1024 float4, 4 per thread
        #pragma unroll
        for (int i = 0; i < 4; i++) {
            int slot = tid + i * 256;     // 0..1023
            int r  = slot >> 3;           // 0..127
            int kq = slot & 7;            // 0..7
            float4 v = make_float4(0.f, 0.f, 0.f, 0.f);
            if (row0 + r < M) {
                v = *(const float4*)(A + (row0 + r) * 128 + kc + kq * 4);
                if (use_scale) {
                    float4 sc = *(const float4*)(g_scale + kc + kq * 4);
                    float4 sf = *(const float4*)(g_shift + kc + kq * 4);
                    v.x = fmaf(v.x, sc.x, sf.x);
                    v.y = fmaf(v.y, sc.y, sf.y);
                    v.z = fmaf(v.z, sc.z, sf.z);
                    v.w = fmaf(v.w, sc.w, sf.w);
                }
            }
            v.x = tf32_of(v.x); v.y = tf32_of(v.y); v.z = tf32_of(v.z); v.w = tf32_of(v.w);
            *(float4*)&As[r][kq * 4] = v;
        }
        // stage B chunk: 32 x 128 floats, row-major [k][n]
        #pragma unroll
        for (int i = 0; i < 4; i++) {
            int slot = tid + i * 256;
            int k  = slot >> 5;           // 0..31
            int nq = slot & 31;           // 0..31
            float4 v = *(const float4*)(B + (kc + k) * 128 + nq * 4);
            v.x = tf32_of(v.x); v.y = tf32_of(v.y); v.z = tf32_of(v.z); v.w = tf32_of(v.w);
            *(float4*)&Bs[k][nq * 4] = v;
        }
        __syncthreads();

        #pragma unroll
        for (int ks = 0; ks < KC; ks += 8) {
            float a[2][4];
            int ar = warpM * 32 + (lane >> 2);
            int ac = ks + (lane & 3);
            #pragma unroll
            for (int m = 0; m < 2; m++) {
                a[m][0] = As[ar + m * 16][ac];
                a[m][1] = As[ar + m * 16 + 8][ac];
                a[m][2] = As[ar + m * 16][ac + 4];
                a[m][3] = As[ar + m * 16 + 8][ac + 4];
            }
            #pragma unroll
            for (int j = 0; j < 8; j++) {
                int bn = warpN * 64 + j * 8 + (lane >> 2);
                float b0 = Bs[ks + (lane & 3)][bn];
                float b1 = Bs[ks + (lane & 3) + 4][bn];
                mma_tf32(c[0][j], a[0], b0, b1);
                mma_tf32(c[1][j], a[1], b0, b1);
            }
        }
        __syncthreads();
    }

    // epilogue: fp16 store + fused attention logit partials
    #pragma unroll
    for (int m = 0; m < 2; m++) {
        int lr0 = warpM * 32 + m * 16 + (lane >> 2);   // local row of c0,c1
        int lr1 = lr0 + 8;                             // local row of c2,c3
        int rr0 = row0 + lr0;
        int rr1 = row0 + lr1;
        float ps0[2] = {0.f, 0.f}, pd0[2] = {0.f, 0.f};
        float ps1[2] = {0.f, 0.f}, pd1[2] = {0.f, 0.f};
        #pragma unroll
        for (int j = 0; j < 8; j++) {
            int cn = warpN * 64 + j * 8 + (lane & 3) * 2;
            float s0 = a_src[cn], s1 = a_src[cn + 1];
            float d0 = a_dst[cn], d1 = a_dst[cn + 1];
            int hh = j >> 2;
            ps0[hh] = fmaf(c[m][j][0], s0, fmaf(c[m][j][1], s1, ps0[hh]));
            pd0[hh] = fmaf(c[m][j][0], d0, fmaf(c[m][j][1], d1, pd0[hh]));
            ps1[hh] = fmaf(c[m][j][2], s0, fmaf(c[m][j][3], s1, ps1[hh]));
            pd1[hh] = fmaf(c[m][j][2], d0, fmaf(c[m][j][3], d1, pd1[hh]));
            if (rr0 < M)
                *(__half2*)(&g_h[rr0 * 128 + cn]) = __floats2half2_rn(c[m][j][0], c[m][j][1]);
            if (rr1 < M)
                *(__half2*)(&g_h[rr1 * 128 + cn]) = __floats2half2_rn(c[m][j][2], c[m][j][3]);
        }
        int h0 = warpN * 2;
        if (rr0 < M) {
            atomicAdd(&sA[lr0][h0],     ps0[0]);
            atomicAdd(&sA[lr0][h0 + 1], ps0[1]);
            atomicAdd(&sD[lr0][h0],     pd0[0]);
            atomicAdd(&sD[lr0][h0 + 1], pd0[1]);
        }
        if (rr1 < M) {
            atomicAdd(&sA[lr1][h0],     ps1[0]);
            atomicAdd(&sA[lr1][h0 + 1], ps1[1]);
            atomicAdd(&sD[lr1][h0],     pd1[0]);
            atomicAdd(&sD[lr1][h0 + 1], pd1[1]);
        }
    }
    __syncthreads();
    #pragma unroll
    for (int l = 0; l < 2; l++) {
        int idx = tid * 2 + l;
        int r = idx >> 2, h = idx & 3;
        if (row0 + r < M) {
            g_as[(row0 + r) * NH + h] = sA[r][h];
            g_ad[(row0 + r) * NH + h] = sD[r][h];
        }
    }
}

// ---------------- GAT aggregation: one WARP per dst node + fused BN stats ----------------
__global__ __launch_bounds__(256) void gat_agg(const float* __restrict__ bias, int n) {
    __shared__ int   s_idx[8][32];
    __shared__ float s_ex [8][128];
    __shared__ float sbn[256];

    int tid  = threadIdx.x;
    int w    = tid >> 5;
    int lane = tid & 31;
    int head = lane >> 3;

    sbn[tid] = 0.f;
    __syncthreads();

    int d = blockIdx.x * 8 + w;
    if (d < n) {
        int beg = g_off[d];
        int deg = g_off[d + 1] - beg;
        float4 adv = ((const float4*)g_ad)[d];

        float4 sumex = make_float4(0.f, 0.f, 0.f, 0.f);
        float acc0 = 0.f, acc1 = 0.f, acc2 = 0.f, acc3 = 0.f;

        for (int base = 0; base < deg; base += 32) {
            int k = base + lane;
            if (k < deg) {
                int s = g_csr[beg + k];
                float4 e = f4lrelu(f4add(((const float4*)g_as)[s], adv));
                float4 ex = make_float4(__expf(e.x), __expf(e.y), __expf(e.z), __expf(e.w));
                sumex = f4add(sumex, ex);
                s_idx[w][lane] = s;
                *(float4*)&s_ex[w][lane * 4] = ex;
            }
            __syncwarp();
            int cnt = min(32, deg - base);
            if (cnt == 32) {
                #pragma unroll 8
                for (int j = 0; j < 32; j++) {
                    int   s  = s_idx[w][j];
                    float wt = s_ex[w][j * 4 + head];
                    uint2 pk = *(const uint2*)(&g_h[s * HD + lane * 4]);
                    __half2* hp = reinterpret_cast<__half2*>(&pk);
                    float2 f0 = __half22float2(hp[0]);
                    float2 f1 = __half22float2(hp[1]);
                    acc0 = fmaf(f0.x, wt, acc0);
                    acc1 = fmaf(f0.y, wt, acc1);
                    acc2 = fmaf(f1.x, wt, acc2);
                    acc3 = fmaf(f1.y, wt, acc3);
                }
            } else {
                #pragma unroll 4
                for (int j = 0; j < cnt; j++) {
                    int   s  = s_idx[w][j];
                    float wt = s_ex[w][j * 4 + head];
                    uint2 pk = *(const uint2*)(&g_h[s * HD + lane * 4]);
                    __half2* hp = reinterpret_cast<__half2*>(&pk);
                    float2 f0 = __half22float2(hp[0]);
                    float2 f1 = __half22float2(hp[1]);
                    acc0 = fmaf(f0.x, wt, acc0);
                    acc1 = fmaf(f0.y, wt, acc1);
                    acc2 = fmaf(f1.x, wt, acc2);
                    acc3 = fmaf(f1.y, wt, acc3);
                }
            }
            __syncwarp();
        }

        #pragma unroll
        for (int o = 16; o; o >>= 1) {
            sumex.x += __shfl_xor_sync(0xffffffffu, sumex.x, o);
            sumex.y += __shfl_xor_sync(0xffffffffu, sumex.y, o);
            sumex.z += __shfl_xor_sync(0xffffffffu, sumex.z, o);
            sumex.w += __shfl_xor_sync(0xffffffffu, sumex.w, o);
        }
        float sv = (head == 0) ? sumex.x : (head == 1) ? sumex.y
                 : (head == 2) ? sumex.z : sumex.w;
        float inv = 1.0f / (sv + 1e-16f);

        float4 b = *(const float4*)(bias + lane * 4);
        float o0 = fmaxf(fmaf(acc0, inv, b.x), 0.f);
        float o1 = fmaxf(fmaf(acc1, inv, b.y), 0.f);
        float o2 = fmaxf(fmaf(acc2, inv, b.z), 0.f);
        float o3 = fmaxf(fmaf(acc3, inv, b.w), 0.f);
        *(float4*)(&g_x2[d * HD + lane * 4]) = make_float4(o0, o1, o2, o3);

        int c = lane * 4;
        atomicAdd(&sbn[c + 0], o0);
        atomicAdd(&sbn[c + 1], o1);
        atomicAdd(&sbn[c + 2], o2);
        atomicAdd(&sbn[c + 3], o3);
        atomicAdd(&sbn[128 + c + 0], o0 * o0);
        atomicAdd(&sbn[128 + c + 1], o1 * o1);
        atomicAdd(&sbn[128 + c + 2], o2 * o2);
        atomicAdd(&sbn[128 + c + 3], o3 * o3);
    }
    __syncthreads();
    atomicAdd(&g_bn[tid], sbn[tid]);
}

// ---------------- BN finalize ----------------
__global__ void bn_final(const float* __restrict__ gamma, const float* __restrict__ beta, int n) {
    int c = threadIdx.x;
    float fn = (float)n;
    float mu  = g_bn[c] / fn;
    float var = g_bn[HD + c] / fn - mu * mu;
    float inv = rsqrtf(var + 1e-5f);
    float sc  = gamma[c] * inv;
    g_scale[c] = sc;
    g_shift[c] = beta[c] - mu * sc;
    g_bn[c] = 0.f;
    g_bn[HD + c] = 0.f;
}

// ---------------- pooling: batch sorted -> segmented register accumulation ----------------
__global__ __launch_bounds__(128) void pool_kernel(const int* __restrict__ batch, int n, int chunk) {
    int i0 = blockIdx.x * chunk;
    if (i0 >= n) return;
    int i1 = min(n, i0 + chunk);
    int t  = threadIdx.x;
    float acc = 0.f;
    int cur = batch[i0];
    int run = 0;
    for (int i = i0; i < i1; i++) {
        int g = batch[i];
        if (g != cur) {
            atomicAdd(&g_pool[cur * HD + t], acc);
            if (t == 0) atomicAdd(&g_cnt[cur], run);
            acc = 0.f; run = 0; cur = g;
        }
        acc += g_x2[i * HD + t];
        run++;
    }
    atomicAdd(&g_pool[cur * HD + t], acc);
    if (t == 0) atomicAdd(&g_cnt[cur], run);
}

// ---------------- MLP head ----------------
__global__ __launch_bounds__(128) void head_kernel(const float* __restrict__ L1W,
                                                   const float* __restrict__ L1b,
                                                   const float* __restrict__ L2W,
                                                   const float* __restrict__ L2b,
                                                   float* __restrict__ out) {
    int g = blockIdx.x, t = threadIdx.x;
    __shared__ float p[128], r0[128], r1[128];
    int c = g_cnt[g];
    float denom = (float)(c > 0 ? c : 1);
    p[t] = fmaf(g_pool[g * HD + t] / denom, g_scale[t], g_shift[t]);
    g_pool[g * HD + t] = 0.f;
    if (t == 0) g_cnt[g] = 0;
    __syncthreads();
    float acc = L1b[t];
    #pragma unroll 8
    for (int k = 0; k < 128; k++)
        acc = fmaf(p[k], L1W[k * HD + t], acc);
    float z = fmaxf(acc, 0.f);
    r0[t] = z * L2W[t * 2 + 0];
    r1[t] = z * L2W[t * 2 + 1];
    __syncthreads();
    for (int o = 64; o; o >>= 1) {
        if (t < o) { r0[t] += r0[t + o]; r1[t] += r1[t + o]; }
        __syncthreads();
    }
    if (t == 0) {
        out[g * 2 + 0] = r0[0] + L2b[0];
        out[g * 2 + 1] = r1[0] + L2b[1];
    }
}

// ---------------- launch ----------------
extern "C" void kernel_launch(void* const* d_in, const int* in_sizes, int n_in,
                              void* d_out, int out_size) {
    const float* x    = (const float*)d_in[0];
    const int*   ei   = (const int*)  d_in[1];
    const int*   batch= (const int*)  d_in[2];
    const float* W1   = (const float*)d_in[3];
    const float* a1s  = (const float*)d_in[4];
    const float* a1d  = (const float*)d_in[5];
    const float* b1   = (const float*)d_in[6];
    const float* bn1g = (const float*)d_in[7];
    const float* bn1b = (const float*)d_in[8];
    const float* W2   = (const float*)d_in[9];
    const float* a2s  = (const float*)d_in[10];
    const float* a2d  = (const float*)d_in[11];
    const float* b2   = (const float*)d_in[12];
    const float* bn2g = (const float*)d_in[13];
    const float* bn2b = (const float*)d_in[14];
    const float* L1W  = (const float*)d_in[15];
    const float* L1b  = (const float*)d_in[16];
    const float* L2W  = (const float*)d_in[17];
    const float* L2b  = (const float*)d_in[18];

    int n = in_sizes[0] / HD;
    int E = in_sizes[1] / 2;
    int G = out_size / 2;
    int ET = E + n;

    count_kernel<<<(ET + 255) / 256, 256>>>(ei, E, n);
    scan_kernel <<<1, 1024>>>(n);
    fill_kernel <<<(ET + 255) / 256, 256>>>(ei, E, n);

    int gb  = (n + 127) / 128;
    int agb = (n + 7) / 8;

    gemm_tc<<<gb, 256>>>(x, W1, n, 0, 0, a1s, a1d);
    gat_agg<<<agb, 256>>>(b1, n);
    bn_final<<<1, 128>>>(bn1g, bn1b, n);

    gemm_tc<<<gb, 256>>>(nullptr, W2, n, 1, 1, a2s, a2d);
    gat_agg<<<agb, 256>>>(b2, n);
    bn_final<<<1, 128>>>(bn2g, bn2b, n);

    pool_kernel<<<(n + 255) / 256, 128>>>(batch, n, 256);
    head_kernel<<<G, 128>>>(L1W, L1b, L2W, L2b, (float*)d_out);
}